// round 8
// baseline (speedup 1.0000x reference)
#include <cuda_runtime.h>
#include <cuda_bf16.h>
#include <math.h>
#include <stdint.h>

#define B_ 8
#define N_ 1024
#define M_ 1024
#define D_ 256
#define H_ 4
#define P_ 128
#define C_ 64
#define CP_ 32   // C/2 pairs

// -------- device scratch: bf16x2-packed hi/lo operands (pairs along K dim) --------
__device__ uint32_t g_qh[B_ * H_ * N_ * CP_];
__device__ uint32_t g_ql[B_ * H_ * N_ * CP_];
__device__ uint32_t g_kh[B_ * H_ * M_ * CP_];
__device__ uint32_t g_kl[B_ * H_ * M_ * CP_];
__device__ uint32_t g_vh[B_ * H_ * M_ * CP_];
__device__ uint32_t g_vl[B_ * H_ * M_ * CP_];
__device__ uint32_t g_eh[P_ * D_ / 2];
__device__ uint32_t g_el[P_ * D_ / 2];
__device__ uint32_t g_wsh[3 * D_ * D_ / 2];
__device__ uint32_t g_wsl[3 * D_ * D_ / 2];

// ---------------- helpers ----------------
__device__ __forceinline__ void split2(float v0, float v1, uint32_t& hp, uint32_t& lp) {
    __nv_bfloat16 h0 = __float2bfloat16_rn(v0);
    __nv_bfloat16 h1 = __float2bfloat16_rn(v1);
    __nv_bfloat16 l0 = __float2bfloat16_rn(v0 - __bfloat162float(h0));
    __nv_bfloat16 l1 = __float2bfloat16_rn(v1 - __bfloat162float(h1));
    hp = (uint32_t)__bfloat16_as_ushort(h0) | ((uint32_t)__bfloat16_as_ushort(h1) << 16);
    lp = (uint32_t)__bfloat16_as_ushort(l0) | ((uint32_t)__bfloat16_as_ushort(l1) << 16);
}

__device__ __forceinline__ uint32_t prmtb(uint32_t a, uint32_t b, uint32_t sel) {
    uint32_t r;
    asm("prmt.b32 %0, %1, %2, %3;" : "=r"(r) : "r"(a), "r"(b), "r"(sel));
    return r;
}

__device__ __forceinline__ void mma16(float d[4], const uint32_t a[4], const uint32_t b[2]) {
    asm volatile(
        "mma.sync.aligned.m16n8k16.row.col.f32.bf16.bf16.f32 "
        "{%0,%1,%2,%3}, {%4,%5,%6,%7}, {%8,%9}, {%0,%1,%2,%3};"
        : "+f"(d[0]), "+f"(d[1]), "+f"(d[2]), "+f"(d[3])
        : "r"(a[0]), "r"(a[1]), "r"(a[2]), "r"(a[3]), "r"(b[0]), "r"(b[1]));
}

// ---------------- fused smem layout (32-bit words) ----------------
// K-staging (128 rows x 32 pairs, stride 36) and V-staging (64 mp x 64 cols,
// stride 72) SHARE the same two 4608-word buffers (never live simultaneously).
#define S_STRIDE  1036   // fp32 logits; packed probs: hi [0,512), lo [518,1030)
#define KB_STRIDE 36
#define VB_STRIDE 72
#define KH0_OFF   33152
#define KL0_OFF   37760
#define KH1_OFF   42368
#define KL1_OFF   46976
#define SP_STRIDE 132
#define SP_OFF    51584
#define SMEM_WORDS 55808
#define SMEM_BYTES (SMEM_WORDS * 4)   // 223232 B

// ============================================================================
// Kernel 0: split W/emb into packed bf16x2 hi/lo pairs (along d).
// ============================================================================
__global__ __launch_bounds__(256) void split_kernel(
    const float* __restrict__ emb, const float* __restrict__ Wq,
    const float* __restrict__ Wk, const float* __restrict__ Wv)
{
    const int i = blockIdx.x * 256 + threadIdx.x;
    float v0, v1;
    uint32_t *oh, *ol;
    int idx;
    if (i < P_ * D_ / 2) {
        v0 = emb[2 * i]; v1 = emb[2 * i + 1]; oh = g_eh; ol = g_el; idx = i;
    } else {
        const int j = i - P_ * D_ / 2;
        const int which = j >> 15;
        const int jj = j & 32767;
        const float* W = (which == 0) ? Wq : (which == 1) ? Wk : Wv;
        v0 = W[2 * jj]; v1 = W[2 * jj + 1]; oh = g_wsh; ol = g_wsl; idx = j;
    }
    uint32_t hp, lp;
    split2(v0, v1, hp, lp);
    oh[idx] = hp;
    ol[idx] = lp;
}

// ============================================================================
// Kernel 1: QKV projection, split-bf16 m16n8k16 (3-MMA). (unchanged from R7)
// ============================================================================
#define PJ_STRIDE 20
__global__ __launch_bounds__(256, 2) void proj_kernel(
    const float* __restrict__ Xq, const float* __restrict__ Xk,
    const float* __restrict__ Xv,
    const float* __restrict__ bq, const float* __restrict__ bk,
    const float* __restrict__ bv)
{
    const int which = blockIdx.z;
    const float* X    = (which == 0) ? Xq : (which == 1) ? Xk : Xv;
    const float* bias = (which == 0) ? bq : (which == 1) ? bk : bv;
    uint32_t* outh    = (which == 0) ? g_qh : (which == 1) ? g_kh : g_vh;
    uint32_t* outl    = (which == 0) ? g_ql : (which == 1) ? g_kl : g_vl;
    const uint32_t* wh_base = g_wsh + which * (D_ * D_ / 2);
    const uint32_t* wl_base = g_wsl + which * (D_ * D_ / 2);

    const int r0 = blockIdx.x * 64;
    const int j0 = blockIdx.y * 64;

    __shared__ uint32_t Xh[2][64 * PJ_STRIDE], Xl[2][64 * PJ_STRIDE];
    __shared__ uint32_t Wh[2][64 * PJ_STRIDE], Wl[2][64 * PJ_STRIDE];

    const int tid  = threadIdx.x;
    const int w    = tid >> 5;
    const int lane = tid & 31;
    const int gid  = lane >> 2;
    const int tg   = lane & 3;
    const int wr   = w & 3;
    const int wc   = w >> 2;
    const int ar0  = wr * 16 + gid;

    const int srow = tid >> 2;
    const int sc   = tid & 3;

    float4 xa = *(const float4*)&X[(size_t)(r0 + srow) * D_ + sc * 8];
    float4 xb = *(const float4*)&X[(size_t)(r0 + srow) * D_ + sc * 8 + 4];
    uint4  wh = *(const uint4*)&wh_base[(size_t)(j0 + srow) * (D_ / 2) + sc * 4];
    uint4  wl = *(const uint4*)&wl_base[(size_t)(j0 + srow) * (D_ / 2) + sc * 4];

    float hh[4][4] = {}, hl[4][4] = {}, lh[4][4] = {};

    for (int mc = 0; mc < 8; mc++) {
        const int bsel = mc & 1;
        {
            uint4 xh4, xl4;
            split2(xa.x, xa.y, xh4.x, xl4.x);
            split2(xa.z, xa.w, xh4.y, xl4.y);
            split2(xb.x, xb.y, xh4.z, xl4.z);
            split2(xb.z, xb.w, xh4.w, xl4.w);
            *(uint4*)&Xh[bsel][srow * PJ_STRIDE + sc * 4] = xh4;
            *(uint4*)&Xl[bsel][srow * PJ_STRIDE + sc * 4] = xl4;
            *(uint4*)&Wh[bsel][srow * PJ_STRIDE + sc * 4] = wh;
            *(uint4*)&Wl[bsel][srow * PJ_STRIDE + sc * 4] = wl;
        }
        if (mc < 7) {
            const int kc = (mc + 1) * 32;
            xa = *(const float4*)&X[(size_t)(r0 + srow) * D_ + kc + sc * 8];
            xb = *(const float4*)&X[(size_t)(r0 + srow) * D_ + kc + sc * 8 + 4];
            wh = *(const uint4*)&wh_base[(size_t)(j0 + srow) * (D_ / 2) + kc / 2 + sc * 4];
            wl = *(const uint4*)&wl_base[(size_t)(j0 + srow) * (D_ / 2) + kc / 2 + sc * 4];
        }
        __syncthreads();

        const uint32_t* xhb = Xh[bsel];
        const uint32_t* xlb = Xl[bsel];
        const uint32_t* whb = Wh[bsel];
        const uint32_t* wlb = Wl[bsel];
#pragma unroll
        for (int kb = 0; kb < 2; kb++) {
            const int c0 = kb * 8 + tg;
            uint32_t ah[4], al[4];
            ah[0] = xhb[ar0 * PJ_STRIDE + c0];
            ah[1] = xhb[(ar0 + 8) * PJ_STRIDE + c0];
            ah[2] = xhb[ar0 * PJ_STRIDE + c0 + 4];
            ah[3] = xhb[(ar0 + 8) * PJ_STRIDE + c0 + 4];
            al[0] = xlb[ar0 * PJ_STRIDE + c0];
            al[1] = xlb[(ar0 + 8) * PJ_STRIDE + c0];
            al[2] = xlb[ar0 * PJ_STRIDE + c0 + 4];
            al[3] = xlb[(ar0 + 8) * PJ_STRIDE + c0 + 4];
#pragma unroll
            for (int ns = 0; ns < 4; ns++) {
                const int br = wc * 32 + ns * 8 + gid;
                uint32_t bhf[2] = {whb[br * PJ_STRIDE + c0], whb[br * PJ_STRIDE + c0 + 4]};
                uint32_t blf[2] = {wlb[br * PJ_STRIDE + c0], wlb[br * PJ_STRIDE + c0 + 4]};
                mma16(hh[ns], ah, bhf);
                mma16(hl[ns], ah, blf);
                mma16(lh[ns], al, bhf);
            }
        }
        __syncthreads();
    }

#pragma unroll
    for (int ns = 0; ns < 4; ns++) {
        const int col = j0 + wc * 32 + ns * 8 + 2 * tg;
        const float b0 = bias[col], b1 = bias[col + 1];
        const int h = col >> 6, cpair = (col & 63) >> 1;
#pragma unroll
        for (int half = 0; half < 2; half++) {
            const int r = r0 + wr * 16 + gid + half * 8;
            const int bb = r >> 10, l = r & 1023;
            const size_t idx = (((size_t)(bb * H_ + h) * N_) + l) * CP_ + cpair;
            const float v0 = hh[ns][half * 2 + 0] + hl[ns][half * 2 + 0] + lh[ns][half * 2 + 0] + b0;
            const float v1 = hh[ns][half * 2 + 1] + hl[ns][half * 2 + 1] + lh[ns][half * 2 + 1] + b1;
            uint32_t hp, lp;
            split2(v0, v1, hp, lp);
            outh[idx] = hp;
            outl[idx] = lp;
        }
    }
}

// ============================================================================
// Kernel 2: FUSED sp + scores + gather/factor/mask + softmax + attn + AV.
// 512 threads; 128-row chunks (8 sync phases per GEMM); K/V share staging.
// ============================================================================
__global__ __launch_bounds__(512, 1) void fused_kernel(
    const float* __restrict__ factor, const int* __restrict__ eidx,
    const unsigned char* __restrict__ kmask,
    float* __restrict__ attn, float* __restrict__ hidden)
{
    extern __shared__ float smf[];
    float*    S   = smf;
    uint32_t* Su  = (uint32_t*)smf;
    uint32_t* KH0 = (uint32_t*)(smf + KH0_OFF);
    uint32_t* KL0 = (uint32_t*)(smf + KL0_OFF);
    uint32_t* KH1 = (uint32_t*)(smf + KH1_OFF);
    uint32_t* KL1 = (uint32_t*)(smf + KL1_OFF);
    float*    Sp  = smf + SP_OFF;

    const int tid  = threadIdx.x;
    const int w    = tid >> 5;
    const int lane = tid & 31;
    const int gid  = lane >> 2;
    const int tg   = lane & 3;
    const int wm   = w & 7;
    const int mt   = w >> 3;
    const int bh = blockIdx.y, b = bh >> 2, h = bh & 3;
    const int n0 = blockIdx.x * 32;
    const int r0 = mt * 16 + gid;

    // K staging: 128 rows x 32 pairs; thread -> 2 uint4 per array
    const int kst_r = tid >> 3;          // 0..63 (second half at +64)
    const int kst_c = (tid & 7) * 4;
    // V repack: 64 mp x 64 cols; thread handles mp=vmp and mp=vmp+32
    const int vmp = tid >> 4;            // 0..31
    const int vcp = (tid & 15) * 2;

    const uint32_t* kh_base = g_kh + (size_t)bh * M_ * CP_;
    const uint32_t* kl_base = g_kl + (size_t)bh * M_ * CP_;
    const uint32_t* vh_base = g_vh + (size_t)bh * M_ * CP_;
    const uint32_t* vl_base = g_vl + (size_t)bh * M_ * CP_;

    // ---------- LDG Q + emb (emb = one 128-row chunk) ----------
    uint2 q2h, q2l;
    uint4 eh0, eh1, el0, el1;
    {
        const uint32_t* qh = g_qh + ((size_t)bh * N_ + n0) * CP_;
        const uint32_t* ql = g_ql + ((size_t)bh * N_ + n0) * CP_;
        q2h = ((const uint2*)qh)[tid];
        q2l = ((const uint2*)ql)[tid];
        eh0 = *(const uint4*)&g_eh[(size_t)kst_r * (D_ / 2) + h * CP_ + kst_c];
        eh1 = *(const uint4*)&g_eh[(size_t)(64 + kst_r) * (D_ / 2) + h * CP_ + kst_c];
        el0 = *(const uint4*)&g_el[(size_t)kst_r * (D_ / 2) + h * CP_ + kst_c];
        el1 = *(const uint4*)&g_el[(size_t)(64 + kst_r) * (D_ / 2) + h * CP_ + kst_c];
    }
    // stage Q (32 rows) through KH0/KL0
    {
        const int qr = tid >> 4, qc = (tid & 15) * 2;
        *(uint2*)&KH0[qr * KB_STRIDE + qc] = q2h;
        *(uint2*)&KL0[qr * KB_STRIDE + qc] = q2l;
    }
    __syncthreads();

    // ---------- preload Q hi+lo fragments ----------
    uint32_t qfh[4][4], qfl[4][4];
#pragma unroll
    for (int kb = 0; kb < 4; kb++) {
        const int c0 = kb * 8 + tg;
        qfh[kb][0] = KH0[r0 * KB_STRIDE + c0];
        qfh[kb][1] = KH0[(r0 + 8) * KB_STRIDE + c0];
        qfh[kb][2] = KH0[r0 * KB_STRIDE + c0 + 4];
        qfh[kb][3] = KH0[(r0 + 8) * KB_STRIDE + c0 + 4];
        qfl[kb][0] = KL0[r0 * KB_STRIDE + c0];
        qfl[kb][1] = KL0[(r0 + 8) * KB_STRIDE + c0];
        qfl[kb][2] = KL0[r0 * KB_STRIDE + c0 + 4];
        qfl[kb][3] = KL0[(r0 + 8) * KB_STRIDE + c0 + 4];
    }
    __syncthreads();

    // ---------- stage emb (128 rows) into KH0/KL0; prefetch K chunk 0 ----------
    *(uint4*)&KH0[kst_r * KB_STRIDE + kst_c]        = eh0;
    *(uint4*)&KH0[(64 + kst_r) * KB_STRIDE + kst_c] = eh1;
    *(uint4*)&KL0[kst_r * KB_STRIDE + kst_c]        = el0;
    *(uint4*)&KL0[(64 + kst_r) * KB_STRIDE + kst_c] = el1;
    uint4 kph0 = *(const uint4*)&kh_base[(size_t)tid * 4];
    uint4 kph1 = *(const uint4*)&kh_base[2048 + (size_t)tid * 4];
    uint4 kpl0 = *(const uint4*)&kl_base[(size_t)tid * 4];
    uint4 kpl1 = *(const uint4*)&kl_base[2048 + (size_t)tid * 4];
    __syncthreads();

    // ---------- SP: Sp(32x128) = Q · emb_h^T (single phase, 2 n-groups) ----------
    {
        float hh[2][4] = {}, hl[2][4] = {}, lh[2][4] = {};
#pragma unroll
        for (int kb = 0; kb < 4; kb++) {
            const int bc = kb * 8 + tg;
#pragma unroll
            for (int g = 0; g < 2; g++) {
                const int br = g * 64 + wm * 8 + gid;
                uint32_t bhf[2] = {KH0[br * KB_STRIDE + bc], KH0[br * KB_STRIDE + bc + 4]};
                uint32_t blf[2] = {KL0[br * KB_STRIDE + bc], KL0[br * KB_STRIDE + bc + 4]};
                mma16(hh[g], qfh[kb], bhf);
                mma16(hl[g], qfh[kb], blf);
                mma16(lh[g], qfl[kb], bhf);
            }
        }
#pragma unroll
        for (int g = 0; g < 2; g++) {
            const int col = g * 64 + wm * 8 + 2 * tg;
            *(float2*)(Sp + r0 * SP_STRIDE + col) =
                make_float2(hh[g][0] + hl[g][0] + lh[g][0], hh[g][1] + hl[g][1] + lh[g][1]);
            *(float2*)(Sp + (r0 + 8) * SP_STRIDE + col) =
                make_float2(hh[g][2] + hl[g][2] + lh[g][2], hh[g][3] + hl[g][3] + lh[g][3]);
        }
    }
    __syncthreads();   // emb reads done before GEMM1 overwrites KH0

    // ---------- GEMM1: S(32x1024) = Q · K^T (8 chunks x 128 rows) ----------
    for (int mc = 0; mc < 8; mc++) {
        uint32_t* Khb = (mc & 1) ? KH1 : KH0;
        uint32_t* Klb = (mc & 1) ? KL1 : KL0;
        *(uint4*)&Khb[kst_r * KB_STRIDE + kst_c]        = kph0;
        *(uint4*)&Khb[(64 + kst_r) * KB_STRIDE + kst_c] = kph1;
        *(uint4*)&Klb[kst_r * KB_STRIDE + kst_c]        = kpl0;
        *(uint4*)&Klb[(64 + kst_r) * KB_STRIDE + kst_c] = kpl1;
        if (mc < 7) {
            const size_t off = (size_t)(mc + 1) * 4096;
            kph0 = *(const uint4*)&kh_base[off + (size_t)tid * 4];
            kph1 = *(const uint4*)&kh_base[off + 2048 + (size_t)tid * 4];
            kpl0 = *(const uint4*)&kl_base[off + (size_t)tid * 4];
            kpl1 = *(const uint4*)&kl_base[off + 2048 + (size_t)tid * 4];
        }
        __syncthreads();

        float hh[2][4] = {}, hl[2][4] = {}, lh[2][4] = {};
#pragma unroll
        for (int kb = 0; kb < 4; kb++) {
            const int bc = kb * 8 + tg;
#pragma unroll
            for (int g = 0; g < 2; g++) {
                const int br = g * 64 + wm * 8 + gid;
                uint32_t bhf[2] = {Khb[br * KB_STRIDE + bc], Khb[br * KB_STRIDE + bc + 4]};
                uint32_t blf[2] = {Klb[br * KB_STRIDE + bc], Klb[br * KB_STRIDE + bc + 4]};
                mma16(hh[g], qfh[kb], bhf);
                mma16(hl[g], qfh[kb], blf);
                mma16(lh[g], qfl[kb], bhf);
            }
        }
#pragma unroll
        for (int g = 0; g < 2; g++) {
            const int col = mc * 128 + g * 64 + wm * 8 + 2 * tg;
            *(float2*)(S + r0 * S_STRIDE + col) =
                make_float2(hh[g][0] + hl[g][0] + lh[g][0], hh[g][1] + hl[g][1] + lh[g][1]);
            *(float2*)(S + (r0 + 8) * S_STRIDE + col) =
                make_float2(hh[g][2] + hl[g][2] + lh[g][2], hh[g][3] + hl[g][3] + lh[g][3]);
        }
    }
    __syncthreads();

    // prefetch V chunk 0 (128 rows; two mp-halves per thread)
    uint2 pvh0a = *(const uint2*)&vh_base[(size_t)vmp * 64 + vcp];
    uint2 pvh1a = *(const uint2*)&vh_base[(size_t)vmp * 64 + 32 + vcp];
    uint2 pvl0a = *(const uint2*)&vl_base[(size_t)vmp * 64 + vcp];
    uint2 pvl1a = *(const uint2*)&vl_base[(size_t)vmp * 64 + 32 + vcp];
    uint2 pvh0b = *(const uint2*)&vh_base[2048 + (size_t)vmp * 64 + vcp];
    uint2 pvh1b = *(const uint2*)&vh_base[2048 + (size_t)vmp * 64 + 32 + vcp];
    uint2 pvl0b = *(const uint2*)&vl_base[2048 + (size_t)vmp * 64 + vcp];
    uint2 pvl1b = *(const uint2*)&vl_base[2048 + (size_t)vmp * 64 + 32 + vcp];

    // ---------- epilogue: gather sp, factor, scale, mask ----------
    {
        const int half = tid >> 8, t2 = tid & 255;
        const int c4 = t2 * 4;
#pragma unroll 4
        for (int it = 0; it < 16; it++) {
            const int row = it * 2 + half;
            const size_t gbase = ((size_t)(b * N_ + n0 + row)) * M_ + c4;
            float4 sc = *(float4*)(S + row * S_STRIDE + c4);
            int4   id = *(const int4*)(eidx + gbase);
            float4 fa = *(const float4*)(factor + gbase);
            const float* sprow = Sp + row * SP_STRIDE;
            float e0 = fa.x * (sc.x + sprow[id.x]) * 0.125f;
            float e1 = fa.y * (sc.y + sprow[id.y]) * 0.125f;
            float e2 = fa.z * (sc.z + sprow[id.z]) * 0.125f;
            float e3 = fa.w * (sc.w + sprow[id.w]) * 0.125f;
            const unsigned char* km = kmask + b * M_ + c4;
            if (km[0]) e0 = -INFINITY;
            if (km[1]) e1 = -INFINITY;
            if (km[2]) e2 = -INFINITY;
            if (km[3]) e3 = -INFINITY;
            *(float4*)(S + row * S_STRIDE + c4) = make_float4(e0, e1, e2, e3);
        }
    }
    __syncthreads();

    // ---------- softmax: warp w owns rows 2w, 2w+1 ----------
#pragma unroll
    for (int rr = 0; rr < 2; rr++) {
        const int row = w * 2 + rr;
        float vals[32];
        float mx = -INFINITY;
#pragma unroll
        for (int j = 0; j < 8; j++) {
            float4 v = *(float4*)(S + row * S_STRIDE + (j * 32 + lane) * 4);
            vals[j * 4 + 0] = v.x; vals[j * 4 + 1] = v.y;
            vals[j * 4 + 2] = v.z; vals[j * 4 + 3] = v.w;
            mx = fmaxf(mx, fmaxf(fmaxf(v.x, v.y), fmaxf(v.z, v.w)));
        }
#pragma unroll
        for (int off = 16; off > 0; off >>= 1)
            mx = fmaxf(mx, __shfl_xor_sync(0xffffffffu, mx, off));
        float sum = 0.f;
#pragma unroll
        for (int i = 0; i < 32; i++) { vals[i] = __expf(vals[i] - mx); sum += vals[i]; }
#pragma unroll
        for (int off = 16; off > 0; off >>= 1)
            sum += __shfl_xor_sync(0xffffffffu, sum, off);
        const float inv = 1.0f / sum;
        const size_t abase = ((size_t)(bh * N_ + n0 + row)) * M_;
#pragma unroll
        for (int j = 0; j < 8; j++) {
            const int c4 = (j * 32 + lane) * 4;
            const float p0 = vals[j * 4 + 0] * inv, p1 = vals[j * 4 + 1] * inv;
            const float p2 = vals[j * 4 + 2] * inv, p3 = vals[j * 4 + 3] * inv;
            *(float4*)(attn + abase + c4) = make_float4(p0, p1, p2, p3);
            uint32_t hp0, lp0, hp1, lp1;
            split2(p0, p1, hp0, lp0);
            split2(p2, p3, hp1, lp1);
            const int c2 = c4 >> 1;
            *(uint2*)(Su + row * S_STRIDE + c2)       = make_uint2(hp0, hp1);
            *(uint2*)(Su + row * S_STRIDE + 518 + c2) = make_uint2(lp0, lp1);
        }
    }

    // ---------- AV: hidden(32x64) = P · V (8 chunks x 128 m-rows) ----------
    // V staging reuses the K region with VB_STRIDE=72 (64 mp x 64 cols).
    uint32_t* VH0 = KH0;
    uint32_t* VL0 = KL0;
    uint32_t* VH1 = KH1;
    uint32_t* VL1 = KL1;
    float avhh[4] = {}, avhl[4] = {}, avlh[4] = {};
    for (int kc = 0; kc < 8; kc++) {
        uint32_t* VHb = (kc & 1) ? VH1 : VH0;
        uint32_t* VLb = (kc & 1) ? VL1 : VL0;
        {   // repack + STS both mp-halves: pair-along-M via PRMT 2x2 transpose
            uint4 oh, ol;
            oh.x = prmtb(pvh0a.x, pvh1a.x, 0x5410); oh.y = prmtb(pvh0a.x, pvh1a.x, 0x7632);
            oh.z = prmtb(pvh0a.y, pvh1a.y, 0x5410); oh.w = prmtb(pvh0a.y, pvh1a.y, 0x7632);
            ol.x = prmtb(pvl0a.x, pvl1a.x, 0x5410); ol.y = prmtb(pvl0a.x, pvl1a.x, 0x7632);
            ol.z = prmtb(pvl0a.y, pvl1a.y, 0x5410); ol.w = prmtb(pvl0a.y, pvl1a.y, 0x7632);
            *(uint4*)&VHb[vmp * VB_STRIDE + (tid & 15) * 4] = oh;
            *(uint4*)&VLb[vmp * VB_STRIDE + (tid & 15) * 4] = ol;
            oh.x = prmtb(pvh0b.x, pvh1b.x, 0x5410); oh.y = prmtb(pvh0b.x, pvh1b.x, 0x7632);
            oh.z = prmtb(pvh0b.y, pvh1b.y, 0x5410); oh.w = prmtb(pvh0b.y, pvh1b.y, 0x7632);
            ol.x = prmtb(pvl0b.x, pvl1b.x, 0x5410); ol.y = prmtb(pvl0b.x, pvl1b.x, 0x7632);
            ol.z = prmtb(pvl0b.y, pvl1b.y, 0x5410); ol.w = prmtb(pvl0b.y, pvl1b.y, 0x7632);
            *(uint4*)&VHb[(vmp + 32) * VB_STRIDE + (tid & 15) * 4] = oh;
            *(uint4*)&VLb[(vmp + 32) * VB_STRIDE + (tid & 15) * 4] = ol;
        }
        if (kc < 7) {
            const size_t off = (size_t)(kc + 1) * 4096;
            pvh0a = *(const uint2*)&vh_base[off + (size_t)vmp * 64 + vcp];
            pvh1a = *(const uint2*)&vh_base[off + (size_t)vmp * 64 + 32 + vcp];
            pvl0a = *(const uint2*)&vl_base[off + (size_t)vmp * 64 + vcp];
            pvl1a = *(const uint2*)&vl_base[off + (size_t)vmp * 64 + 32 + vcp];
            pvh0b = *(const uint2*)&vh_base[off + 2048 + (size_t)vmp * 64 + vcp];
            pvh1b = *(const uint2*)&vh_base[off + 2048 + (size_t)vmp * 64 + 32 + vcp];
            pvl0b = *(const uint2*)&vl_base[off + 2048 + (size_t)vmp * 64 + vcp];
            pvl1b = *(const uint2*)&vl_base[off + 2048 + (size_t)vmp * 64 + 32 + vcp];
        }
        __syncthreads();

#pragma unroll
        for (int kb = 0; kb < 8; kb++) {
            const int cb = kc * 64 + kb * 8;
            uint32_t ah[4], al[4];
            ah[0] = Su[r0 * S_STRIDE + cb + tg];
            ah[1] = Su[(r0 + 8) * S_STRIDE + cb + tg];
            ah[2] = Su[r0 * S_STRIDE + cb + tg + 4];
            ah[3] = Su[(r0 + 8) * S_STRIDE + cb + tg + 4];
            al[0] = Su[r0 * S_STRIDE + 518 + cb + tg];
            al[1] = Su[(r0 + 8) * S_STRIDE + 518 + cb + tg];
            al[2] = Su[r0 * S_STRIDE + 518 + cb + tg + 4];
            al[3] = Su[(r0 + 8) * S_STRIDE + 518 + cb + tg + 4];
            uint32_t bhf[2], blf[2];
            bhf[0] = VHb[(kb * 8 + tg) * VB_STRIDE + wm * 8 + gid];
            bhf[1] = VHb[(kb * 8 + tg + 4) * VB_STRIDE + wm * 8 + gid];
            blf[0] = VLb[(kb * 8 + tg) * VB_STRIDE + wm * 8 + gid];
            blf[1] = VLb[(kb * 8 + tg + 4) * VB_STRIDE + wm * 8 + gid];
            mma16(avhh, ah, bhf);
            mma16(avhl, ah, blf);
            mma16(avlh, al, bhf);
        }
        __syncthreads();   // all warps done reading buffer before next STS
    }

    // store hidden
    {
        const int row = n0 + r0;
        const int col = h * 64 + wm * 8 + 2 * tg;
        *(float2*)(hidden + ((size_t)b * N_ + row) * D_ + col) =
            make_float2(avhh[0] + avhl[0] + avlh[0], avhh[1] + avhl[1] + avlh[1]);
        *(float2*)(hidden + ((size_t)b * N_ + row + 8) * D_ + col) =
            make_float2(avhh[2] + avhl[2] + avlh[2], avhh[3] + avhl[3] + avlh[3]);
    }
}

// ============================================================================
// Launch
// ============================================================================
extern "C" void kernel_launch(void* const* d_in, const int* in_sizes, int n_in,
                              void* d_out, int out_size)
{
    const float* input_q = (const float*)d_in[0];
    const float* input_k = (const float*)d_in[1];
    const float* input_v = (const float*)d_in[2];
    const float* Wq = (const float*)d_in[3];
    const float* bq = (const float*)d_in[4];
    const float* Wk = (const float*)d_in[5];
    const float* bk = (const float*)d_in[6];
    const float* Wv = (const float*)d_in[7];
    const float* bv = (const float*)d_in[8];
    const float* emb_table = (const float*)d_in[9];
    const float* factor = (const float*)d_in[10];
    const int* eidx = (const int*)d_in[11];
    const unsigned char* kmask = (const unsigned char*)d_in[12];

    float* hidden = (float*)d_out;                          // (B,N,D)
    float* attn   = (float*)d_out + (size_t)B_ * N_ * D_;   // (B,H,N,M)

    static int smem_set = 0;
    if (!smem_set) {
        cudaFuncSetAttribute(fused_kernel,
                             cudaFuncAttributeMaxDynamicSharedMemorySize, SMEM_BYTES);
        smem_set = 1;
    }

    split_kernel<<<(P_ * D_ / 2 + 3 * D_ * D_ / 2) / 256, 256>>>(emb_table, Wq, Wk, Wv);

    proj_kernel<<<dim3((B_ * N_) / 64, D_ / 64, 3), 256>>>(
        input_q, input_k, input_v, bq, bk, bv);

    fused_kernel<<<dim3(N_ / 32, B_ * H_), 512, SMEM_BYTES>>>(
        factor, eidx, kmask, attn, hidden);
}

// round 9
// speedup vs baseline: 1.0922x; 1.0922x over previous
#include <cuda_runtime.h>
#include <cuda_bf16.h>
#include <math.h>
#include <stdint.h>

#define B_ 8
#define N_ 1024
#define M_ 1024
#define D_ 256
#define H_ 4
#define P_ 128
#define C_ 64
#define CP_ 32   // C/2 pairs

// -------- device scratch: bf16x2-packed hi/lo operands (pairs along K dim) --------
__device__ uint32_t g_qh[B_ * H_ * N_ * CP_];
__device__ uint32_t g_ql[B_ * H_ * N_ * CP_];
__device__ uint32_t g_kh[B_ * H_ * M_ * CP_];
__device__ uint32_t g_kl[B_ * H_ * M_ * CP_];
__device__ uint32_t g_vh[B_ * H_ * M_ * CP_];
__device__ uint32_t g_vl[B_ * H_ * M_ * CP_];
__device__ uint32_t g_eh[P_ * D_ / 2];
__device__ uint32_t g_el[P_ * D_ / 2];
__device__ uint32_t g_wsh[3 * D_ * D_ / 2];
__device__ uint32_t g_wsl[3 * D_ * D_ / 2];

// ---------------- helpers ----------------
__device__ __forceinline__ void split2(float v0, float v1, uint32_t& hp, uint32_t& lp) {
    __nv_bfloat16 h0 = __float2bfloat16_rn(v0);
    __nv_bfloat16 h1 = __float2bfloat16_rn(v1);
    __nv_bfloat16 l0 = __float2bfloat16_rn(v0 - __bfloat162float(h0));
    __nv_bfloat16 l1 = __float2bfloat16_rn(v1 - __bfloat162float(h1));
    hp = (uint32_t)__bfloat16_as_ushort(h0) | ((uint32_t)__bfloat16_as_ushort(h1) << 16);
    lp = (uint32_t)__bfloat16_as_ushort(l0) | ((uint32_t)__bfloat16_as_ushort(l1) << 16);
}

__device__ __forceinline__ uint32_t prmtb(uint32_t a, uint32_t b, uint32_t sel) {
    uint32_t r;
    asm("prmt.b32 %0, %1, %2, %3;" : "=r"(r) : "r"(a), "r"(b), "r"(sel));
    return r;
}

__device__ __forceinline__ void mma16(float d[4], const uint32_t a[4], const uint32_t b[2]) {
    asm volatile(
        "mma.sync.aligned.m16n8k16.row.col.f32.bf16.bf16.f32 "
        "{%0,%1,%2,%3}, {%4,%5,%6,%7}, {%8,%9}, {%0,%1,%2,%3};"
        : "+f"(d[0]), "+f"(d[1]), "+f"(d[2]), "+f"(d[3])
        : "r"(a[0]), "r"(a[1]), "r"(a[2]), "r"(a[3]), "r"(b[0]), "r"(b[1]));
}

// ---------------- fused smem layout (32-bit words) ----------------
#define S_STRIDE  1036   // fp32 logits; packed probs: hi [0,512), lo [518,1030)
#define KB_STRIDE 36     // K/Q/emb staging: 64 rows x 32 pairs (+4 pad)
#define VB_STRIDE 72     // V staging (pair-along-M): 32 mp x 64 cols (+8 pad)
#define KH0_OFF   33152
#define KL0_OFF   35456
#define KH1_OFF   37760
#define KL1_OFF   40064
#define VH0_OFF   42368
#define VL0_OFF   44672
#define VH1_OFF   46976
#define VL1_OFF   49280
#define SP_STRIDE 132
#define SP_OFF    51584
#define SMEM_WORDS 55808
#define SMEM_BYTES (SMEM_WORDS * 4)   // 223232 B

// ============================================================================
// Kernel 0: split W/emb into packed bf16x2 hi/lo pairs (along d).
// ============================================================================
__global__ __launch_bounds__(256) void split_kernel(
    const float* __restrict__ emb, const float* __restrict__ Wq,
    const float* __restrict__ Wk, const float* __restrict__ Wv)
{
    const int i = blockIdx.x * 256 + threadIdx.x;
    float v0, v1;
    uint32_t *oh, *ol;
    int idx;
    if (i < P_ * D_ / 2) {
        v0 = emb[2 * i]; v1 = emb[2 * i + 1]; oh = g_eh; ol = g_el; idx = i;
    } else {
        const int j = i - P_ * D_ / 2;
        const int which = j >> 15;
        const int jj = j & 32767;
        const float* W = (which == 0) ? Wq : (which == 1) ? Wk : Wv;
        v0 = W[2 * jj]; v1 = W[2 * jj + 1]; oh = g_wsh; ol = g_wsl; idx = j;
    }
    uint32_t hp, lp;
    split2(v0, v1, hp, lp);
    oh[idx] = hp;
    ol[idx] = lp;
}

// ============================================================================
// Kernel 1: QKV projection, split-bf16 m16n8k16 (3-MMA).
// 64x64 tile, 256 thr, K=256 in 8 chunks of 32, double-buffered,
// ONE barrier per chunk (STS overlaps previous chunk's MMA).
// ============================================================================
#define PJ_STRIDE 20
__global__ __launch_bounds__(256, 2) void proj_kernel(
    const float* __restrict__ Xq, const float* __restrict__ Xk,
    const float* __restrict__ Xv,
    const float* __restrict__ bq, const float* __restrict__ bk,
    const float* __restrict__ bv)
{
    const int which = blockIdx.z;
    const float* X    = (which == 0) ? Xq : (which == 1) ? Xk : Xv;
    const float* bias = (which == 0) ? bq : (which == 1) ? bk : bv;
    uint32_t* outh    = (which == 0) ? g_qh : (which == 1) ? g_kh : g_vh;
    uint32_t* outl    = (which == 0) ? g_ql : (which == 1) ? g_kl : g_vl;
    const uint32_t* wh_base = g_wsh + which * (D_ * D_ / 2);
    const uint32_t* wl_base = g_wsl + which * (D_ * D_ / 2);

    const int r0 = blockIdx.x * 64;
    const int j0 = blockIdx.y * 64;

    __shared__ uint32_t Xh[2][64 * PJ_STRIDE], Xl[2][64 * PJ_STRIDE];
    __shared__ uint32_t Wh[2][64 * PJ_STRIDE], Wl[2][64 * PJ_STRIDE];

    const int tid  = threadIdx.x;
    const int w    = tid >> 5;
    const int lane = tid & 31;
    const int gid  = lane >> 2;
    const int tg   = lane & 3;
    const int wr   = w & 3;
    const int wc   = w >> 2;
    const int ar0  = wr * 16 + gid;

    const int srow = tid >> 2;
    const int sc   = tid & 3;

    float4 xa = *(const float4*)&X[(size_t)(r0 + srow) * D_ + sc * 8];
    float4 xb = *(const float4*)&X[(size_t)(r0 + srow) * D_ + sc * 8 + 4];
    uint4  wh = *(const uint4*)&wh_base[(size_t)(j0 + srow) * (D_ / 2) + sc * 4];
    uint4  wl = *(const uint4*)&wl_base[(size_t)(j0 + srow) * (D_ / 2) + sc * 4];

    float hh[4][4] = {}, hl[4][4] = {}, lh[4][4] = {};

    for (int mc = 0; mc < 8; mc++) {
        const int bsel = mc & 1;
        {
            uint4 xh4, xl4;
            split2(xa.x, xa.y, xh4.x, xl4.x);
            split2(xa.z, xa.w, xh4.y, xl4.y);
            split2(xb.x, xb.y, xh4.z, xl4.z);
            split2(xb.z, xb.w, xh4.w, xl4.w);
            *(uint4*)&Xh[bsel][srow * PJ_STRIDE + sc * 4] = xh4;
            *(uint4*)&Xl[bsel][srow * PJ_STRIDE + sc * 4] = xl4;
            *(uint4*)&Wh[bsel][srow * PJ_STRIDE + sc * 4] = wh;
            *(uint4*)&Wl[bsel][srow * PJ_STRIDE + sc * 4] = wl;
        }
        if (mc < 7) {
            const int kc = (mc + 1) * 32;
            xa = *(const float4*)&X[(size_t)(r0 + srow) * D_ + kc + sc * 8];
            xb = *(const float4*)&X[(size_t)(r0 + srow) * D_ + kc + sc * 8 + 4];
            wh = *(const uint4*)&wh_base[(size_t)(j0 + srow) * (D_ / 2) + kc / 2 + sc * 4];
            wl = *(const uint4*)&wl_base[(size_t)(j0 + srow) * (D_ / 2) + kc / 2 + sc * 4];
        }
        __syncthreads();

        const uint32_t* xhb = Xh[bsel];
        const uint32_t* xlb = Xl[bsel];
        const uint32_t* whb = Wh[bsel];
        const uint32_t* wlb = Wl[bsel];
#pragma unroll
        for (int kb = 0; kb < 2; kb++) {
            const int c0 = kb * 8 + tg;
            uint32_t ah[4], al[4];
            ah[0] = xhb[ar0 * PJ_STRIDE + c0];
            ah[1] = xhb[(ar0 + 8) * PJ_STRIDE + c0];
            ah[2] = xhb[ar0 * PJ_STRIDE + c0 + 4];
            ah[3] = xhb[(ar0 + 8) * PJ_STRIDE + c0 + 4];
            al[0] = xlb[ar0 * PJ_STRIDE + c0];
            al[1] = xlb[(ar0 + 8) * PJ_STRIDE + c0];
            al[2] = xlb[ar0 * PJ_STRIDE + c0 + 4];
            al[3] = xlb[(ar0 + 8) * PJ_STRIDE + c0 + 4];
#pragma unroll
            for (int ns = 0; ns < 4; ns++) {
                const int br = wc * 32 + ns * 8 + gid;
                uint32_t bhf[2] = {whb[br * PJ_STRIDE + c0], whb[br * PJ_STRIDE + c0 + 4]};
                uint32_t blf[2] = {wlb[br * PJ_STRIDE + c0], wlb[br * PJ_STRIDE + c0 + 4]};
                mma16(hh[ns], ah, bhf);
                mma16(hl[ns], ah, blf);
                mma16(lh[ns], al, bhf);
            }
        }
        // no trailing sync: double buffers + next iteration's barrier protect reuse
    }

#pragma unroll
    for (int ns = 0; ns < 4; ns++) {
        const int col = j0 + wc * 32 + ns * 8 + 2 * tg;
        const float b0 = bias[col], b1 = bias[col + 1];
        const int h = col >> 6, cpair = (col & 63) >> 1;
#pragma unroll
        for (int half = 0; half < 2; half++) {
            const int r = r0 + wr * 16 + gid + half * 8;
            const int bb = r >> 10, l = r & 1023;
            const size_t idx = (((size_t)(bb * H_ + h) * N_) + l) * CP_ + cpair;
            const float v0 = hh[ns][half * 2 + 0] + hl[ns][half * 2 + 0] + lh[ns][half * 2 + 0] + b0;
            const float v1 = hh[ns][half * 2 + 1] + hl[ns][half * 2 + 1] + lh[ns][half * 2 + 1] + b1;
            uint32_t hp, lp;
            split2(v0, v1, hp, lp);
            outh[idx] = hp;
            outl[idx] = lp;
        }
    }
}

// ============================================================================
// Kernel 2: FUSED sp + scores + gather/factor/mask + softmax + attn + AV.
// 512 threads, split-bf16 m16n8k16, 64-row chunks, double-buffered (R7 struct).
// ============================================================================
__global__ __launch_bounds__(512, 1) void fused_kernel(
    const float* __restrict__ factor, const int* __restrict__ eidx,
    const unsigned char* __restrict__ kmask,
    float* __restrict__ attn, float* __restrict__ hidden)
{
    extern __shared__ float smf[];
    float*    S   = smf;                       // 32 x 1036 fp32 logits
    uint32_t* Su  = (uint32_t*)smf;            // packed probs alias (in-row)
    uint32_t* KH0 = (uint32_t*)(smf + KH0_OFF);
    uint32_t* KL0 = (uint32_t*)(smf + KL0_OFF);
    uint32_t* KH1 = (uint32_t*)(smf + KH1_OFF);
    uint32_t* KL1 = (uint32_t*)(smf + KL1_OFF);
    uint32_t* VH0 = (uint32_t*)(smf + VH0_OFF);
    uint32_t* VL0 = (uint32_t*)(smf + VL0_OFF);
    uint32_t* VH1 = (uint32_t*)(smf + VH1_OFF);
    uint32_t* VL1 = (uint32_t*)(smf + VL1_OFF);
    float*    Sp  = smf + SP_OFF;

    const int tid  = threadIdx.x;
    const int w    = tid >> 5;
    const int lane = tid & 31;
    const int gid  = lane >> 2;
    const int tg   = lane & 3;
    const int wm   = w & 7;
    const int mt   = w >> 3;
    const int bh = blockIdx.y, b = bh >> 2, h = bh & 3;
    const int n0 = blockIdx.x * 32;
    const int r0 = mt * 16 + gid;

    const int kst_r = tid >> 3;          // 0..63
    const int kst_c = (tid & 7) * 4;     // 0..28
    const int vmp = tid >> 4;            // 0..31
    const int vcp = (tid & 15) * 2;

    const uint32_t* kh_base = g_kh + (size_t)bh * M_ * CP_;
    const uint32_t* kl_base = g_kl + (size_t)bh * M_ * CP_;
    const uint32_t* vh_base = g_vh + (size_t)bh * M_ * CP_;
    const uint32_t* vl_base = g_vl + (size_t)bh * M_ * CP_;

    // ---------- stage Q (32 rows x 32 pairs) through KH0/KL0 ----------
    {
        const uint32_t* qh = g_qh + ((size_t)bh * N_ + n0) * CP_;
        const uint32_t* ql = g_ql + ((size_t)bh * N_ + n0) * CP_;
        uint2 q2h = ((const uint2*)qh)[tid];
        uint2 q2l = ((const uint2*)ql)[tid];
        const int qr = tid >> 4, qc = (tid & 15) * 2;
        *(uint2*)&KH0[qr * KB_STRIDE + qc] = q2h;
        *(uint2*)&KL0[qr * KB_STRIDE + qc] = q2l;
    }
    uint4 eph, epl;
    eph = *(const uint4*)&g_eh[(size_t)kst_r * (D_ / 2) + h * CP_ + kst_c];
    epl = *(const uint4*)&g_el[(size_t)kst_r * (D_ / 2) + h * CP_ + kst_c];
    __syncthreads();

    // ---------- preload Q hi+lo fragments (4 k16-blocks) ----------
    uint32_t qfh[4][4], qfl[4][4];
#pragma unroll
    for (int kb = 0; kb < 4; kb++) {
        const int c0 = kb * 8 + tg;
        qfh[kb][0] = KH0[r0 * KB_STRIDE + c0];
        qfh[kb][1] = KH0[(r0 + 8) * KB_STRIDE + c0];
        qfh[kb][2] = KH0[r0 * KB_STRIDE + c0 + 4];
        qfh[kb][3] = KH0[(r0 + 8) * KB_STRIDE + c0 + 4];
        qfl[kb][0] = KL0[r0 * KB_STRIDE + c0];
        qfl[kb][1] = KL0[(r0 + 8) * KB_STRIDE + c0];
        qfl[kb][2] = KL0[r0 * KB_STRIDE + c0 + 4];
        qfl[kb][3] = KL0[(r0 + 8) * KB_STRIDE + c0 + 4];
    }
    __syncthreads();

    // ---------- SP: Sp(32x128) = Q · emb_h^T (2 chunks) ----------
#pragma unroll
    for (int pc = 0; pc < 2; pc++) {
        uint32_t* Khb = pc ? KH1 : KH0;
        uint32_t* Klb = pc ? KL1 : KL0;
        *(uint4*)&Khb[kst_r * KB_STRIDE + kst_c] = eph;
        *(uint4*)&Klb[kst_r * KB_STRIDE + kst_c] = epl;
        if (pc == 0) {
            eph = *(const uint4*)&g_eh[(size_t)(64 + kst_r) * (D_ / 2) + h * CP_ + kst_c];
            epl = *(const uint4*)&g_el[(size_t)(64 + kst_r) * (D_ / 2) + h * CP_ + kst_c];
        }
        __syncthreads();

        float hh[4] = {}, hl[4] = {}, lh[4] = {};
#pragma unroll
        for (int kb = 0; kb < 4; kb++) {
            const int br = wm * 8 + gid, bc = kb * 8 + tg;
            uint32_t bhf[2] = {Khb[br * KB_STRIDE + bc], Khb[br * KB_STRIDE + bc + 4]};
            uint32_t blf[2] = {Klb[br * KB_STRIDE + bc], Klb[br * KB_STRIDE + bc + 4]};
            mma16(hh, qfh[kb], bhf);
            mma16(hl, qfh[kb], blf);
            mma16(lh, qfl[kb], bhf);
        }
        const int col = pc * 64 + wm * 8 + 2 * tg;
        *(float2*)(Sp + r0 * SP_STRIDE + col) =
            make_float2(hh[0] + hl[0] + lh[0], hh[1] + hl[1] + lh[1]);
        *(float2*)(Sp + (r0 + 8) * SP_STRIDE + col) =
            make_float2(hh[2] + hl[2] + lh[2], hh[3] + hl[3] + lh[3]);
    }
    uint4 kph = *(const uint4*)&kh_base[(size_t)tid * 4];
    uint4 kpl = *(const uint4*)&kl_base[(size_t)tid * 4];

    // ---------- GEMM1: S(32x1024) = Q · K^T (16 chunks, 1 sync each) ----------
    for (int mc = 0; mc < 16; mc++) {
        uint32_t* Khb = (mc & 1) ? KH1 : KH0;
        uint32_t* Klb = (mc & 1) ? KL1 : KL0;
        *(uint4*)&Khb[kst_r * KB_STRIDE + kst_c] = kph;
        *(uint4*)&Klb[kst_r * KB_STRIDE + kst_c] = kpl;
        if (mc < 15) {
            const size_t off = (size_t)(mc + 1) * 2048;
            kph = *(const uint4*)&kh_base[off + (size_t)tid * 4];
            kpl = *(const uint4*)&kl_base[off + (size_t)tid * 4];
        }
        __syncthreads();

        float hh[4] = {}, hl[4] = {}, lh[4] = {};
#pragma unroll
        for (int kb = 0; kb < 4; kb++) {
            const int br = wm * 8 + gid, bc = kb * 8 + tg;
            uint32_t bhf[2] = {Khb[br * KB_STRIDE + bc], Khb[br * KB_STRIDE + bc + 4]};
            uint32_t blf[2] = {Klb[br * KB_STRIDE + bc], Klb[br * KB_STRIDE + bc + 4]};
            mma16(hh, qfh[kb], bhf);
            mma16(hl, qfh[kb], blf);
            mma16(lh, qfl[kb], bhf);
        }
        const int col = mc * 64 + wm * 8 + 2 * tg;
        *(float2*)(S + r0 * S_STRIDE + col) =
            make_float2(hh[0] + hl[0] + lh[0], hh[1] + hl[1] + lh[1]);
        *(float2*)(S + (r0 + 8) * S_STRIDE + col) =
            make_float2(hh[2] + hl[2] + lh[2], hh[3] + hl[3] + lh[3]);
    }
    __syncthreads();

    // prefetch V chunk 0 raw pairs (repacked at STS time)
    uint2 pvh0 = *(const uint2*)&vh_base[(size_t)vmp * 64 + vcp];
    uint2 pvh1 = *(const uint2*)&vh_base[(size_t)vmp * 64 + 32 + vcp];
    uint2 pvl0 = *(const uint2*)&vl_base[(size_t)vmp * 64 + vcp];
    uint2 pvl1 = *(const uint2*)&vl_base[(size_t)vmp * 64 + 32 + vcp];

    // ---------- epilogue: gather sp, factor, scale, mask ----------
    {
        const int half = tid >> 8, t2 = tid & 255;
        const int c4 = t2 * 4;
#pragma unroll 4
        for (int it = 0; it < 16; it++) {
            const int row = it * 2 + half;
            const size_t gbase = ((size_t)(b * N_ + n0 + row)) * M_ + c4;
            float4 sc = *(float4*)(S + row * S_STRIDE + c4);
            int4   id = *(const int4*)(eidx + gbase);
            float4 fa = *(const float4*)(factor + gbase);
            const float* sprow = Sp + row * SP_STRIDE;
            float e0 = fa.x * (sc.x + sprow[id.x]) * 0.125f;
            float e1 = fa.y * (sc.y + sprow[id.y]) * 0.125f;
            float e2 = fa.z * (sc.z + sprow[id.z]) * 0.125f;
            float e3 = fa.w * (sc.w + sprow[id.w]) * 0.125f;
            const unsigned char* km = kmask + b * M_ + c4;
            if (km[0]) e0 = -INFINITY;
            if (km[1]) e1 = -INFINITY;
            if (km[2]) e2 = -INFINITY;
            if (km[3]) e3 = -INFINITY;
            *(float4*)(S + row * S_STRIDE + c4) = make_float4(e0, e1, e2, e3);
        }
    }
    __syncthreads();

    // ---------- softmax: warp w owns rows 2w, 2w+1 ----------
#pragma unroll
    for (int rr = 0; rr < 2; rr++) {
        const int row = w * 2 + rr;
        float vals[32];
        float mx = -INFINITY;
#pragma unroll
        for (int j = 0; j < 8; j++) {
            float4 v = *(float4*)(S + row * S_STRIDE + (j * 32 + lane) * 4);
            vals[j * 4 + 0] = v.x; vals[j * 4 + 1] = v.y;
            vals[j * 4 + 2] = v.z; vals[j * 4 + 3] = v.w;
            mx = fmaxf(mx, fmaxf(fmaxf(v.x, v.y), fmaxf(v.z, v.w)));
        }
#pragma unroll
        for (int off = 16; off > 0; off >>= 1)
            mx = fmaxf(mx, __shfl_xor_sync(0xffffffffu, mx, off));
        float sum = 0.f;
#pragma unroll
        for (int i = 0; i < 32; i++) { vals[i] = __expf(vals[i] - mx); sum += vals[i]; }
#pragma unroll
        for (int off = 16; off > 0; off >>= 1)
            sum += __shfl_xor_sync(0xffffffffu, sum, off);
        const float inv = 1.0f / sum;
        const size_t abase = ((size_t)(bh * N_ + n0 + row)) * M_;
#pragma unroll
        for (int j = 0; j < 8; j++) {
            const int c4 = (j * 32 + lane) * 4;
            const float p0 = vals[j * 4 + 0] * inv, p1 = vals[j * 4 + 1] * inv;
            const float p2 = vals[j * 4 + 2] * inv, p3 = vals[j * 4 + 3] * inv;
            *(float4*)(attn + abase + c4) = make_float4(p0, p1, p2, p3);
            uint32_t hp0, lp0, hp1, lp1;
            split2(p0, p1, hp0, lp0);
            split2(p2, p3, hp1, lp1);
            const int c2 = c4 >> 1;
            *(uint2*)(Su + row * S_STRIDE + c2)       = make_uint2(hp0, hp1);
            *(uint2*)(Su + row * S_STRIDE + 518 + c2) = make_uint2(lp0, lp1);
        }
    }

    // ---------- AV: hidden(32x64) = P · V (16 chunks, repack V to pair-along-M) ----------
    float avhh[4] = {}, avhl[4] = {}, avlh[4] = {};
    for (int kc = 0; kc < 16; kc++) {
        uint32_t* VHb = (kc & 1) ? VH1 : VH0;
        uint32_t* VLb = (kc & 1) ? VL1 : VL0;
        {   // repack + STS: pair-along-M via PRMT 2x2 bf16 transpose
            uint4 oh, ol;
            oh.x = prmtb(pvh0.x, pvh1.x, 0x5410); oh.y = prmtb(pvh0.x, pvh1.x, 0x7632);
            oh.z = prmtb(pvh0.y, pvh1.y, 0x5410); oh.w = prmtb(pvh0.y, pvh1.y, 0x7632);
            ol.x = prmtb(pvl0.x, pvl1.x, 0x5410); ol.y = prmtb(pvl0.x, pvl1.x, 0x7632);
            ol.z = prmtb(pvl0.y, pvl1.y, 0x5410); ol.w = prmtb(pvl0.y, pvl1.y, 0x7632);
            *(uint4*)&VHb[vmp * VB_STRIDE + (tid & 15) * 4] = oh;
            *(uint4*)&VLb[vmp * VB_STRIDE + (tid & 15) * 4] = ol;
        }
        if (kc < 15) {
            const size_t off = (size_t)(kc + 1) * 2048;
            pvh0 = *(const uint2*)&vh_base[off + (size_t)vmp * 64 + vcp];
            pvh1 = *(const uint2*)&vh_base[off + (size_t)vmp * 64 + 32 + vcp];
            pvl0 = *(const uint2*)&vl_base[off + (size_t)vmp * 64 + vcp];
            pvl1 = *(const uint2*)&vl_base[off + (size_t)vmp * 64 + 32 + vcp];
        }
        __syncthreads();

#pragma unroll
        for (int kb = 0; kb < 4; kb++) {
            const int cb = kc * 32 + kb * 8;
            uint32_t ah[4], al[4];
            ah[0] = Su[r0 * S_STRIDE + cb + tg];
            ah[1] = Su[(r0 + 8) * S_STRIDE + cb + tg];
            ah[2] = Su[r0 * S_STRIDE + cb + tg + 4];
            ah[3] = Su[(r0 + 8) * S_STRIDE + cb + tg + 4];
            al[0] = Su[r0 * S_STRIDE + 518 + cb + tg];
            al[1] = Su[(r0 + 8) * S_STRIDE + 518 + cb + tg];
            al[2] = Su[r0 * S_STRIDE + 518 + cb + tg + 4];
            al[3] = Su[(r0 + 8) * S_STRIDE + 518 + cb + tg + 4];
            uint32_t bhf[2], blf[2];
            bhf[0] = VHb[(kb * 8 + tg) * VB_STRIDE + wm * 8 + gid];
            bhf[1] = VHb[(kb * 8 + tg + 4) * VB_STRIDE + wm * 8 + gid];
            blf[0] = VLb[(kb * 8 + tg) * VB_STRIDE + wm * 8 + gid];
            blf[1] = VLb[(kb * 8 + tg + 4) * VB_STRIDE + wm * 8 + gid];
            mma16(avhh, ah, bhf);
            mma16(avhl, ah, blf);
            mma16(avlh, al, bhf);
        }
    }

    // store hidden
    {
        const int row = n0 + r0;
        const int col = h * 64 + wm * 8 + 2 * tg;
        *(float2*)(hidden + ((size_t)b * N_ + row) * D_ + col) =
            make_float2(avhh[0] + avhl[0] + avlh[0], avhh[1] + avhl[1] + avlh[1]);
        *(float2*)(hidden + ((size_t)b * N_ + row + 8) * D_ + col) =
            make_float2(avhh[2] + avhl[2] + avlh[2], avhh[3] + avhl[3] + avlh[3]);
    }
}

// ============================================================================
// Launch
// ============================================================================
extern "C" void kernel_launch(void* const* d_in, const int* in_sizes, int n_in,
                              void* d_out, int out_size)
{
    const float* input_q = (const float*)d_in[0];
    const float* input_k = (const float*)d_in[1];
    const float* input_v = (const float*)d_in[2];
    const float* Wq = (const float*)d_in[3];
    const float* bq = (const float*)d_in[4];
    const float* Wk = (const float*)d_in[5];
    const float* bk = (const float*)d_in[6];
    const float* Wv = (const float*)d_in[7];
    const float* bv = (const float*)d_in[8];
    const float* emb_table = (const float*)d_in[9];
    const float* factor = (const float*)d_in[10];
    const int* eidx = (const int*)d_in[11];
    const unsigned char* kmask = (const unsigned char*)d_in[12];

    float* hidden = (float*)d_out;                          // (B,N,D)
    float* attn   = (float*)d_out + (size_t)B_ * N_ * D_;   // (B,H,N,M)

    static int smem_set = 0;
    if (!smem_set) {
        cudaFuncSetAttribute(fused_kernel,
                             cudaFuncAttributeMaxDynamicSharedMemorySize, SMEM_BYTES);
        smem_set = 1;
    }

    split_kernel<<<(P_ * D_ / 2 + 3 * D_ * D_ / 2) / 256, 256>>>(emb_table, Wq, Wk, Wv);

    proj_kernel<<<dim3((B_ * N_) / 64, D_ / 64, 3), 256>>>(
        input_q, input_k, input_v, bq, bk, bv);

    fused_kernel<<<dim3(N_ / 32, B_ * H_), 512, SMEM_BYTES>>>(
        factor, eidx, kmask, attn, hidden);
}

// round 11
// speedup vs baseline: 1.1996x; 1.0983x over previous
#include <cuda_runtime.h>
#include <cuda_bf16.h>
#include <math.h>
#include <stdint.h>

#define B_ 8
#define N_ 1024
#define M_ 1024
#define D_ 256
#define H_ 4
#define P_ 128
#define C_ 64
#define CP_ 32   // C/2 pairs

// -------- device scratch: bf16x2-packed hi/lo operands (pairs along K dim) --------
__device__ uint32_t g_qh[B_ * H_ * N_ * CP_];
__device__ uint32_t g_ql[B_ * H_ * N_ * CP_];
__device__ uint32_t g_kh[B_ * H_ * M_ * CP_];
__device__ uint32_t g_kl[B_ * H_ * M_ * CP_];
__device__ uint32_t g_vh[B_ * H_ * M_ * CP_];
__device__ uint32_t g_vl[B_ * H_ * M_ * CP_];
__device__ uint32_t g_eh[P_ * D_ / 2];
__device__ uint32_t g_el[P_ * D_ / 2];
__device__ uint32_t g_wsh[3 * D_ * D_ / 2];
__device__ uint32_t g_wsl[3 * D_ * D_ / 2];

// ---------------- helpers ----------------
__device__ __forceinline__ void split2(float v0, float v1, uint32_t& hp, uint32_t& lp) {
    __nv_bfloat16 h0 = __float2bfloat16_rn(v0);
    __nv_bfloat16 h1 = __float2bfloat16_rn(v1);
    __nv_bfloat16 l0 = __float2bfloat16_rn(v0 - __bfloat162float(h0));
    __nv_bfloat16 l1 = __float2bfloat16_rn(v1 - __bfloat162float(h1));
    hp = (uint32_t)__bfloat16_as_ushort(h0) | ((uint32_t)__bfloat16_as_ushort(h1) << 16);
    lp = (uint32_t)__bfloat16_as_ushort(l0) | ((uint32_t)__bfloat16_as_ushort(l1) << 16);
}

__device__ __forceinline__ void mma16(float d[4], const uint32_t a[4], const uint32_t b[2]) {
    asm volatile(
        "mma.sync.aligned.m16n8k16.row.col.f32.bf16.bf16.f32 "
        "{%0,%1,%2,%3}, {%4,%5,%6,%7}, {%8,%9}, {%0,%1,%2,%3};"
        : "+f"(d[0]), "+f"(d[1]), "+f"(d[2]), "+f"(d[3])
        : "r"(a[0]), "r"(a[1]), "r"(a[2]), "r"(a[3]), "r"(b[0]), "r"(b[1]));
}

__device__ __forceinline__ void ldsm4(uint32_t r[4], uint32_t a) {
    asm volatile("ldmatrix.sync.aligned.m8n8.x4.shared.b16 {%0,%1,%2,%3}, [%4];"
        : "=r"(r[0]), "=r"(r[1]), "=r"(r[2]), "=r"(r[3]) : "r"(a));
}
__device__ __forceinline__ void ldsm4t(uint32_t r[4], uint32_t a) {
    asm volatile("ldmatrix.sync.aligned.m8n8.x4.trans.shared.b16 {%0,%1,%2,%3}, [%4];"
        : "=r"(r[0]), "=r"(r[1]), "=r"(r[2]), "=r"(r[3]) : "r"(a));
}

// ---------------- fused smem layout (32-bit words) ----------------
#define S_STRIDE  1036   // fp32 logits; packed probs: hi [0,512), lo [520,1032) (16B-aligned!)
#define LO_OFF    520
#define KB_STRIDE 36     // K/Q/emb/V staging: 64 rows x 32 words (+4 pad)
#define KH0_OFF   33152
#define KL0_OFF   35456
#define KH1_OFF   37760
#define KL1_OFF   40064
#define SP_STRIDE 132
#define SP_OFF    42368
#define SMEM_WORDS 46592
#define SMEM_BYTES (SMEM_WORDS * 4)   // 186368 B

// ============================================================================
// Kernel 0: split W/emb into packed bf16x2 hi/lo pairs (along d).
// ============================================================================
__global__ __launch_bounds__(256) void split_kernel(
    const float* __restrict__ emb, const float* __restrict__ Wq,
    const float* __restrict__ Wk, const float* __restrict__ Wv)
{
    const int i = blockIdx.x * 256 + threadIdx.x;
    float v0, v1;
    uint32_t *oh, *ol;
    int idx;
    if (i < P_ * D_ / 2) {
        v0 = emb[2 * i]; v1 = emb[2 * i + 1]; oh = g_eh; ol = g_el; idx = i;
    } else {
        const int j = i - P_ * D_ / 2;
        const int which = j >> 15;
        const int jj = j & 32767;
        const float* W = (which == 0) ? Wq : (which == 1) ? Wk : Wv;
        v0 = W[2 * jj]; v1 = W[2 * jj + 1]; oh = g_wsh; ol = g_wsl; idx = j;
    }
    uint32_t hp, lp;
    split2(v0, v1, hp, lp);
    oh[idx] = hp;
    ol[idx] = lp;
}

// ============================================================================
// Kernel 1: QKV projection, split-bf16 m16n8k16 (3-MMA). (R9 structure)
// ============================================================================
#define PJ_STRIDE 20
__global__ __launch_bounds__(256, 2) void proj_kernel(
    const float* __restrict__ Xq, const float* __restrict__ Xk,
    const float* __restrict__ Xv,
    const float* __restrict__ bq, const float* __restrict__ bk,
    const float* __restrict__ bv)
{
    const int which = blockIdx.z;
    const float* X    = (which == 0) ? Xq : (which == 1) ? Xk : Xv;
    const float* bias = (which == 0) ? bq : (which == 1) ? bk : bv;
    uint32_t* outh    = (which == 0) ? g_qh : (which == 1) ? g_kh : g_vh;
    uint32_t* outl    = (which == 0) ? g_ql : (which == 1) ? g_kl : g_vl;
    const uint32_t* wh_base = g_wsh + which * (D_ * D_ / 2);
    const uint32_t* wl_base = g_wsl + which * (D_ * D_ / 2);

    const int r0 = blockIdx.x * 64;
    const int j0 = blockIdx.y * 64;

    __shared__ uint32_t Xh[2][64 * PJ_STRIDE], Xl[2][64 * PJ_STRIDE];
    __shared__ uint32_t Wh[2][64 * PJ_STRIDE], Wl[2][64 * PJ_STRIDE];

    const int tid  = threadIdx.x;
    const int w    = tid >> 5;
    const int lane = tid & 31;
    const int gid  = lane >> 2;
    const int tg   = lane & 3;
    const int wr   = w & 3;
    const int wc   = w >> 2;
    const int ar0  = wr * 16 + gid;

    const int srow = tid >> 2;
    const int sc   = tid & 3;

    float4 xa = *(const float4*)&X[(size_t)(r0 + srow) * D_ + sc * 8];
    float4 xb = *(const float4*)&X[(size_t)(r0 + srow) * D_ + sc * 8 + 4];
    uint4  wh = *(const uint4*)&wh_base[(size_t)(j0 + srow) * (D_ / 2) + sc * 4];
    uint4  wl = *(const uint4*)&wl_base[(size_t)(j0 + srow) * (D_ / 2) + sc * 4];

    float hh[4][4] = {}, hl[4][4] = {}, lh[4][4] = {};

    for (int mc = 0; mc < 8; mc++) {
        const int bsel = mc & 1;
        {
            uint4 xh4, xl4;
            split2(xa.x, xa.y, xh4.x, xl4.x);
            split2(xa.z, xa.w, xh4.y, xl4.y);
            split2(xb.x, xb.y, xh4.z, xl4.z);
            split2(xb.z, xb.w, xh4.w, xl4.w);
            *(uint4*)&Xh[bsel][srow * PJ_STRIDE + sc * 4] = xh4;
            *(uint4*)&Xl[bsel][srow * PJ_STRIDE + sc * 4] = xl4;
            *(uint4*)&Wh[bsel][srow * PJ_STRIDE + sc * 4] = wh;
            *(uint4*)&Wl[bsel][srow * PJ_STRIDE + sc * 4] = wl;
        }
        if (mc < 7) {
            const int kc = (mc + 1) * 32;
            xa = *(const float4*)&X[(size_t)(r0 + srow) * D_ + kc + sc * 8];
            xb = *(const float4*)&X[(size_t)(r0 + srow) * D_ + kc + sc * 8 + 4];
            wh = *(const uint4*)&wh_base[(size_t)(j0 + srow) * (D_ / 2) + kc / 2 + sc * 4];
            wl = *(const uint4*)&wl_base[(size_t)(j0 + srow) * (D_ / 2) + kc / 2 + sc * 4];
        }
        __syncthreads();

        const uint32_t* xhb = Xh[bsel];
        const uint32_t* xlb = Xl[bsel];
        const uint32_t* whb = Wh[bsel];
        const uint32_t* wlb = Wl[bsel];
#pragma unroll
        for (int kb = 0; kb < 2; kb++) {
            const int c0 = kb * 8 + tg;
            uint32_t ah[4], al[4];
            ah[0] = xhb[ar0 * PJ_STRIDE + c0];
            ah[1] = xhb[(ar0 + 8) * PJ_STRIDE + c0];
            ah[2] = xhb[ar0 * PJ_STRIDE + c0 + 4];
            ah[3] = xhb[(ar0 + 8) * PJ_STRIDE + c0 + 4];
            al[0] = xlb[ar0 * PJ_STRIDE + c0];
            al[1] = xlb[(ar0 + 8) * PJ_STRIDE + c0];
            al[2] = xlb[ar0 * PJ_STRIDE + c0 + 4];
            al[3] = xlb[(ar0 + 8) * PJ_STRIDE + c0 + 4];
#pragma unroll
            for (int ns = 0; ns < 4; ns++) {
                const int br = wc * 32 + ns * 8 + gid;
                uint32_t bhf[2] = {whb[br * PJ_STRIDE + c0], whb[br * PJ_STRIDE + c0 + 4]};
                uint32_t blf[2] = {wlb[br * PJ_STRIDE + c0], wlb[br * PJ_STRIDE + c0 + 4]};
                mma16(hh[ns], ah, bhf);
                mma16(hl[ns], ah, blf);
                mma16(lh[ns], al, bhf);
            }
        }
    }

#pragma unroll
    for (int ns = 0; ns < 4; ns++) {
        const int col = j0 + wc * 32 + ns * 8 + 2 * tg;
        const float b0 = bias[col], b1 = bias[col + 1];
        const int h = col >> 6, cpair = (col & 63) >> 1;
#pragma unroll
        for (int half = 0; half < 2; half++) {
            const int r = r0 + wr * 16 + gid + half * 8;
            const int bb = r >> 10, l = r & 1023;
            const size_t idx = (((size_t)(bb * H_ + h) * N_) + l) * CP_ + cpair;
            const float v0 = hh[ns][half * 2 + 0] + hl[ns][half * 2 + 0] + lh[ns][half * 2 + 0] + b0;
            const float v1 = hh[ns][half * 2 + 1] + hl[ns][half * 2 + 1] + lh[ns][half * 2 + 1] + b1;
            uint32_t hp, lp;
            split2(v0, v1, hp, lp);
            outh[idx] = hp;
            outl[idx] = lp;
        }
    }
}

// ============================================================================
// Kernel 2: FUSED sp + scores + (gather/factor/mask fused into softmax) + AV.
// 512 threads; ldmatrix fragment loads; V staged raw and read via ldsm.trans;
// K/V share the two staging double-buffers.
// ============================================================================
__global__ __launch_bounds__(512, 1) void fused_kernel(
    const float* __restrict__ factor, const int* __restrict__ eidx,
    const unsigned char* __restrict__ kmask,
    float* __restrict__ attn, float* __restrict__ hidden)
{
    extern __shared__ float smf[];
    float*    S   = smf;                       // 32 x 1036 fp32 logits
    uint32_t* Su  = (uint32_t*)smf;            // packed probs alias (in-row)
    uint32_t* KH0 = (uint32_t*)(smf + KH0_OFF);
    uint32_t* KL0 = (uint32_t*)(smf + KL0_OFF);
    uint32_t* KH1 = (uint32_t*)(smf + KH1_OFF);
    uint32_t* KL1 = (uint32_t*)(smf + KL1_OFF);
    float*    Sp  = smf + SP_OFF;

    const int tid  = threadIdx.x;
    const int w    = tid >> 5;
    const int lane = tid & 31;
    const int gid  = lane >> 2;
    const int tg   = lane & 3;
    const int wm   = w & 7;
    const int mt   = w >> 3;
    const int bh = blockIdx.y, b = bh >> 2, h = bh & 3;
    const int n0 = blockIdx.x * 32;
    const int r0 = mt * 16 + gid;

    const int kst_r = tid >> 3;          // 0..63
    const int kst_c = (tid & 7) * 4;     // 0..28

    // ---- ldmatrix per-lane address offsets (bytes) ----
    const uint32_t smem_u = (uint32_t)__cvta_generic_to_shared(smf);
    const int lg = lane >> 3, lr = lane & 7;
    // B frags (K/emb, non-trans): tiles (k-blocks) per x4
    const uint32_t offKB = (uint32_t)(((wm * 8 + lr) * KB_STRIDE + lg * 4) * 4);
    // B frags (V, trans): rows = raw m
    const uint32_t offVB = (uint32_t)(((lg * 8 + lr) * KB_STRIDE + wm * 4) * 4);
    // A frags (probs in Su, non-trans)
    const uint32_t offAh = (uint32_t)(((mt * 16 + (lg & 1) * 8 + lr) * S_STRIDE + (lg >> 1) * 4) * 4);
    const uint32_t KH0b = smem_u + KH0_OFF * 4;
    const uint32_t KL0b = smem_u + KL0_OFF * 4;
    const uint32_t KH1b = smem_u + KH1_OFF * 4;
    const uint32_t KL1b = smem_u + KL1_OFF * 4;

    const uint32_t* kh_base = g_kh + (size_t)bh * M_ * CP_;
    const uint32_t* kl_base = g_kl + (size_t)bh * M_ * CP_;
    const uint32_t* vh_base = g_vh + (size_t)bh * M_ * CP_;
    const uint32_t* vl_base = g_vl + (size_t)bh * M_ * CP_;

    // ---------- stage Q (32 rows x 32 pairs) through KH0/KL0 ----------
    {
        const uint32_t* qh = g_qh + ((size_t)bh * N_ + n0) * CP_;
        const uint32_t* ql = g_ql + ((size_t)bh * N_ + n0) * CP_;
        uint2 q2h = ((const uint2*)qh)[tid];
        uint2 q2l = ((const uint2*)ql)[tid];
        const int qr = tid >> 4, qc = (tid & 15) * 2;
        *(uint2*)&KH0[qr * KB_STRIDE + qc] = q2h;
        *(uint2*)&KL0[qr * KB_STRIDE + qc] = q2l;
    }
    uint4 eph, epl;
    eph = *(const uint4*)&g_eh[(size_t)kst_r * (D_ / 2) + h * CP_ + kst_c];
    epl = *(const uint4*)&g_el[(size_t)kst_r * (D_ / 2) + h * CP_ + kst_c];
    __syncthreads();

    // ---------- preload Q hi+lo fragments (4 k16-blocks) ----------
    uint32_t qfh[4][4], qfl[4][4];
#pragma unroll
    for (int kb = 0; kb < 4; kb++) {
        const int c0 = kb * 8 + tg;
        qfh[kb][0] = KH0[r0 * KB_STRIDE + c0];
        qfh[kb][1] = KH0[(r0 + 8) * KB_STRIDE + c0];
        qfh[kb][2] = KH0[r0 * KB_STRIDE + c0 + 4];
        qfh[kb][3] = KH0[(r0 + 8) * KB_STRIDE + c0 + 4];
        qfl[kb][0] = KL0[r0 * KB_STRIDE + c0];
        qfl[kb][1] = KL0[(r0 + 8) * KB_STRIDE + c0];
        qfl[kb][2] = KL0[r0 * KB_STRIDE + c0 + 4];
        qfl[kb][3] = KL0[(r0 + 8) * KB_STRIDE + c0 + 4];
    }
    __syncthreads();

    // ---------- SP: Sp(32x128) = Q · emb_h^T (2 chunks) ----------
#pragma unroll
    for (int pc = 0; pc < 2; pc++) {
        uint32_t* Khb = pc ? KH1 : KH0;
        uint32_t* Klb = pc ? KL1 : KL0;
        const uint32_t Khbb = pc ? KH1b : KH0b;
        const uint32_t Klbb = pc ? KL1b : KL0b;
        *(uint4*)&Khb[kst_r * KB_STRIDE + kst_c] = eph;
        *(uint4*)&Klb[kst_r * KB_STRIDE + kst_c] = epl;
        if (pc == 0) {
            eph = *(const uint4*)&g_eh[(size_t)(64 + kst_r) * (D_ / 2) + h * CP_ + kst_c];
            epl = *(const uint4*)&g_el[(size_t)(64 + kst_r) * (D_ / 2) + h * CP_ + kst_c];
        }
        __syncthreads();

        float hh[4] = {}, hl[4] = {}, lh[4] = {};
#pragma unroll
        for (int kbp = 0; kbp < 2; kbp++) {
            uint32_t bh4[4], bl4[4];
            ldsm4(bh4, Khbb + offKB + kbp * 64);
            ldsm4(bl4, Klbb + offKB + kbp * 64);
            mma16(hh, qfh[2 * kbp], bh4);
            mma16(hl, qfh[2 * kbp], bl4);
            mma16(lh, qfl[2 * kbp], bh4);
            mma16(hh, qfh[2 * kbp + 1], bh4 + 2);
            mma16(hl, qfh[2 * kbp + 1], bl4 + 2);
            mma16(lh, qfl[2 * kbp + 1], bh4 + 2);
        }
        const int col = pc * 64 + wm * 8 + 2 * tg;
        *(float2*)(Sp + r0 * SP_STRIDE + col) =
            make_float2(hh[0] + hl[0] + lh[0], hh[1] + hl[1] + lh[1]);
        *(float2*)(Sp + (r0 + 8) * SP_STRIDE + col) =
            make_float2(hh[2] + hl[2] + lh[2], hh[3] + hl[3] + lh[3]);
    }
    uint4 kph = *(const uint4*)&kh_base[(size_t)tid * 4];
    uint4 kpl = *(const uint4*)&kl_base[(size_t)tid * 4];

    // ---------- GEMM1: S(32x1024) = Q · K^T (16 chunks, 1 sync each) ----------
    for (int mc = 0; mc < 16; mc++) {
        uint32_t* Khb = (mc & 1) ? KH1 : KH0;
        uint32_t* Klb = (mc & 1) ? KL1 : KL0;
        const uint32_t Khbb = (mc & 1) ? KH1b : KH0b;
        const uint32_t Klbb = (mc & 1) ? KL1b : KL0b;
        *(uint4*)&Khb[kst_r * KB_STRIDE + kst_c] = kph;
        *(uint4*)&Klb[kst_r * KB_STRIDE + kst_c] = kpl;
        if (mc < 15) {
            const size_t off = (size_t)(mc + 1) * 2048;
            kph = *(const uint4*)&kh_base[off + (size_t)tid * 4];
            kpl = *(const uint4*)&kl_base[off + (size_t)tid * 4];
        }
        __syncthreads();

        float hh[4] = {}, hl[4] = {}, lh[4] = {};
#pragma unroll
        for (int kbp = 0; kbp < 2; kbp++) {
            uint32_t bh4[4], bl4[4];
            ldsm4(bh4, Khbb + offKB + kbp * 64);
            ldsm4(bl4, Klbb + offKB + kbp * 64);
            mma16(hh, qfh[2 * kbp], bh4);
            mma16(hl, qfh[2 * kbp], bl4);
            mma16(lh, qfl[2 * kbp], bh4);
            mma16(hh, qfh[2 * kbp + 1], bh4 + 2);
            mma16(hl, qfh[2 * kbp + 1], bl4 + 2);
            mma16(lh, qfl[2 * kbp + 1], bh4 + 2);
        }
        const int col = mc * 64 + wm * 8 + 2 * tg;
        *(float2*)(S + r0 * S_STRIDE + col) =
            make_float2(hh[0] + hl[0] + lh[0], hh[1] + hl[1] + lh[1]);
        *(float2*)(S + (r0 + 8) * S_STRIDE + col) =
            make_float2(hh[2] + hl[2] + lh[2], hh[3] + hl[3] + lh[3]);
    }
    __syncthreads();

    // prefetch V chunk 0 (raw [m][c] copy — same pattern as K)
    uint4 vph = *(const uint4*)&vh_base[(size_t)tid * 4];
    uint4 vpl = *(const uint4*)&vl_base[(size_t)tid * 4];

    // ---------- softmax with FUSED epilogue: warp w owns rows 2w, 2w+1 ----------
#pragma unroll
    for (int rr = 0; rr < 2; rr++) {
        const int row = w * 2 + rr;
        const size_t gb = ((size_t)(b * N_ + n0 + row)) * M_;
        const float* sprow = Sp + row * SP_STRIDE;
        float vals[32];
        float mx = -INFINITY;
#pragma unroll
        for (int j = 0; j < 8; j++) {
            const int c4 = (j * 32 + lane) * 4;
            float4 sc = *(float4*)(S + row * S_STRIDE + c4);
            int4   id = *(const int4*)(eidx + gb + c4);
            float4 fa = *(const float4*)(factor + gb + c4);
            const uchar4 km = *(const uchar4*)(kmask + b * M_ + c4);
            float e0 = km.x ? -INFINITY : fa.x * (sc.x + sprow[id.x]) * 0.125f;
            float e1 = km.y ? -INFINITY : fa.y * (sc.y + sprow[id.y]) * 0.125f;
            float e2 = km.z ? -INFINITY : fa.z * (sc.z + sprow[id.z]) * 0.125f;
            float e3 = km.w ? -INFINITY : fa.w * (sc.w + sprow[id.w]) * 0.125f;
            vals[j * 4 + 0] = e0; vals[j * 4 + 1] = e1;
            vals[j * 4 + 2] = e2; vals[j * 4 + 3] = e3;
            mx = fmaxf(mx, fmaxf(fmaxf(e0, e1), fmaxf(e2, e3)));
        }
#pragma unroll
        for (int off = 16; off > 0; off >>= 1)
            mx = fmaxf(mx, __shfl_xor_sync(0xffffffffu, mx, off));
        float sum = 0.f;
#pragma unroll
        for (int i = 0; i < 32; i++) { vals[i] = __expf(vals[i] - mx); sum += vals[i]; }
#pragma unroll
        for (int off = 16; off > 0; off >>= 1)
            sum += __shfl_xor_sync(0xffffffffu, sum, off);
        const float inv = 1.0f / sum;
        const size_t abase = ((size_t)(bh * N_ + n0 + row)) * M_;
#pragma unroll
        for (int j = 0; j < 8; j++) {
            const int c4 = (j * 32 + lane) * 4;
            const float p0 = vals[j * 4 + 0] * inv, p1 = vals[j * 4 + 1] * inv;
            const float p2 = vals[j * 4 + 2] * inv, p3 = vals[j * 4 + 3] * inv;
            *(float4*)(attn + abase + c4) = make_float4(p0, p1, p2, p3);
            uint32_t hp0, lp0, hp1, lp1;
            split2(p0, p1, hp0, lp0);
            split2(p2, p3, hp1, lp1);
            const int c2 = c4 >> 1;
            *(uint2*)(Su + row * S_STRIDE + c2)          = make_uint2(hp0, hp1);
            *(uint2*)(Su + row * S_STRIDE + LO_OFF + c2) = make_uint2(lp0, lp1);
        }
    }

    // ---------- AV: hidden(32x64) = P · V (16 chunks; V raw + ldsm.trans) ----------
    float avhh[4] = {}, avhl[4] = {}, avlh[4] = {};
    for (int kc = 0; kc < 16; kc++) {
        uint32_t* Vhb = (kc & 1) ? KH1 : KH0;
        uint32_t* Vlb = (kc & 1) ? KL1 : KL0;
        const uint32_t Vhbb = (kc & 1) ? KH1b : KH0b;
        const uint32_t Vlbb = (kc & 1) ? KL1b : KL0b;
        *(uint4*)&Vhb[kst_r * KB_STRIDE + kst_c] = vph;
        *(uint4*)&Vlb[kst_r * KB_STRIDE + kst_c] = vpl;
        if (kc < 15) {
            const size_t off = (size_t)(kc + 1) * 2048;
            vph = *(const uint4*)&vh_base[off + (size_t)tid * 4];
            vpl = *(const uint4*)&vl_base[off + (size_t)tid * 4];
        }
        __syncthreads();

#pragma unroll
        for (int kbp = 0; kbp < 2; kbp++) {
            uint32_t bh4[4], bl4[4];
            ldsm4t(bh4, Vhbb + offVB + kbp * (32 * KB_STRIDE * 4));
            ldsm4t(bl4, Vlbb + offVB + kbp * (32 * KB_STRIDE * 4));
#pragma unroll
            for (int kk = 0; kk < 2; kk++) {
                const int kb = 2 * kbp + kk;
                const uint32_t cboff = (uint32_t)((kc * 32 + kb * 8) * 4);
                uint32_t ah4[4], al4[4];
                ldsm4(ah4, smem_u + offAh + cboff);
                ldsm4(al4, smem_u + offAh + LO_OFF * 4 + cboff);
                mma16(avhh, ah4, bh4 + 2 * kk);
                mma16(avhl, ah4, bl4 + 2 * kk);
                mma16(avlh, al4, bh4 + 2 * kk);
            }
        }
    }

    // store hidden
    {
        const int row = n0 + r0;
        const int col = h * 64 + wm * 8 + 2 * tg;
        *(float2*)(hidden + ((size_t)b * N_ + row) * D_ + col) =
            make_float2(avhh[0] + avhl[0] + avlh[0], avhh[1] + avhl[1] + avlh[1]);
        *(float2*)(hidden + ((size_t)b * N_ + row + 8) * D_ + col) =
            make_float2(avhh[2] + avhl[2] + avlh[2], avhh[3] + avhl[3] + avlh[3]);
    }
}

// ============================================================================
// Launch
// ============================================================================
extern "C" void kernel_launch(void* const* d_in, const int* in_sizes, int n_in,
                              void* d_out, int out_size)
{
    const float* input_q = (const float*)d_in[0];
    const float* input_k = (const float*)d_in[1];
    const float* input_v = (const float*)d_in[2];
    const float* Wq = (const float*)d_in[3];
    const float* bq = (const float*)d_in[4];
    const float* Wk = (const float*)d_in[5];
    const float* bk = (const float*)d_in[6];
    const float* Wv = (const float*)d_in[7];
    const float* bv = (const float*)d_in[8];
    const float* emb_table = (const float*)d_in[9];
    const float* factor = (const float*)d_in[10];
    const int* eidx = (const int*)d_in[11];
    const unsigned char* kmask = (const unsigned char*)d_in[12];

    float* hidden = (float*)d_out;                          // (B,N,D)
    float* attn   = (float*)d_out + (size_t)B_ * N_ * D_;   // (B,H,N,M)

    static int smem_set = 0;
    if (!smem_set) {
        cudaFuncSetAttribute(fused_kernel,
                             cudaFuncAttributeMaxDynamicSharedMemorySize, SMEM_BYTES);
        smem_set = 1;
    }

    split_kernel<<<(P_ * D_ / 2 + 3 * D_ * D_ / 2) / 256, 256>>>(emb_table, Wq, Wk, Wv);

    proj_kernel<<<dim3((B_ * N_) / 64, D_ / 64, 3), 256>>>(
        input_q, input_k, input_v, bq, bk, bv);

    fused_kernel<<<dim3(N_ / 32, B_ * H_), 512, SMEM_BYTES>>>(
        factor, eidx, kmask, attn, hidden);
}

// round 12
// speedup vs baseline: 1.2119x; 1.0103x over previous
#include <cuda_runtime.h>
#include <cuda_bf16.h>
#include <math.h>
#include <stdint.h>

#define B_ 8
#define N_ 1024
#define M_ 1024
#define D_ 256
#define H_ 4
#define P_ 128
#define C_ 64
#define CP_ 32   // C/2 pairs

// -------- device scratch: bf16x2-packed hi/lo operands (pairs along K dim) --------
__device__ uint32_t g_qh[B_ * H_ * N_ * CP_];
__device__ uint32_t g_ql[B_ * H_ * N_ * CP_];
__device__ uint32_t g_kh[B_ * H_ * M_ * CP_];
__device__ uint32_t g_kl[B_ * H_ * M_ * CP_];
__device__ uint32_t g_vh[B_ * H_ * M_ * CP_];
__device__ uint32_t g_vl[B_ * H_ * M_ * CP_];
__device__ uint32_t g_eh[P_ * D_ / 2];
__device__ uint32_t g_el[P_ * D_ / 2];
__device__ uint32_t g_wsh[3 * D_ * D_ / 2];
__device__ uint32_t g_wsl[3 * D_ * D_ / 2];

// ---------------- helpers ----------------
__device__ __forceinline__ void split2(float v0, float v1, uint32_t& hp, uint32_t& lp) {
    __nv_bfloat16 h0 = __float2bfloat16_rn(v0);
    __nv_bfloat16 h1 = __float2bfloat16_rn(v1);
    __nv_bfloat16 l0 = __float2bfloat16_rn(v0 - __bfloat162float(h0));
    __nv_bfloat16 l1 = __float2bfloat16_rn(v1 - __bfloat162float(h1));
    hp = (uint32_t)__bfloat16_as_ushort(h0) | ((uint32_t)__bfloat16_as_ushort(h1) << 16);
    lp = (uint32_t)__bfloat16_as_ushort(l0) | ((uint32_t)__bfloat16_as_ushort(l1) << 16);
}

__device__ __forceinline__ void mma16(float d[4], const uint32_t a[4], const uint32_t b[2]) {
    asm volatile(
        "mma.sync.aligned.m16n8k16.row.col.f32.bf16.bf16.f32 "
        "{%0,%1,%2,%3}, {%4,%5,%6,%7}, {%8,%9}, {%0,%1,%2,%3};"
        : "+f"(d[0]), "+f"(d[1]), "+f"(d[2]), "+f"(d[3])
        : "r"(a[0]), "r"(a[1]), "r"(a[2]), "r"(a[3]), "r"(b[0]), "r"(b[1]));
}

__device__ __forceinline__ void ldsm4(uint32_t r[4], uint32_t a) {
    asm volatile("ldmatrix.sync.aligned.m8n8.x4.shared.b16 {%0,%1,%2,%3}, [%4];"
        : "=r"(r[0]), "=r"(r[1]), "=r"(r[2]), "=r"(r[3]) : "r"(a));
}
__device__ __forceinline__ void ldsm4t(uint32_t r[4], uint32_t a) {
    asm volatile("ldmatrix.sync.aligned.m8n8.x4.trans.shared.b16 {%0,%1,%2,%3}, [%4];"
        : "=r"(r[0]), "=r"(r[1]), "=r"(r[2]), "=r"(r[3]) : "r"(a));
}

// ---------------- fused smem layout (32-bit words) ----------------
#define S_STRIDE  1036   // fp32 logits; packed probs: hi [0,512), lo [520,1032)
#define LO_OFF    520
#define KB_STRIDE 36     // K/Q/emb/V staging: 64 rows x 32 words (+4 pad)
#define KH0_OFF   33152
#define KL0_OFF   35456
#define KH1_OFF   37760
#define KL1_OFF   40064
#define SP_STRIDE 132
#define SP_OFF    42368
#define SMEM_WORDS 46592
#define SMEM_BYTES (SMEM_WORDS * 4)   // 186368 B

// ============================================================================
// Kernel 0: split W/emb into packed bf16x2 hi/lo pairs (along d).
// ============================================================================
__global__ __launch_bounds__(256) void split_kernel(
    const float* __restrict__ emb, const float* __restrict__ Wq,
    const float* __restrict__ Wk, const float* __restrict__ Wv)
{
    const int i = blockIdx.x * 256 + threadIdx.x;
    float v0, v1;
    uint32_t *oh, *ol;
    int idx;
    if (i < P_ * D_ / 2) {
        v0 = emb[2 * i]; v1 = emb[2 * i + 1]; oh = g_eh; ol = g_el; idx = i;
    } else {
        const int j = i - P_ * D_ / 2;
        const int which = j >> 15;
        const int jj = j & 32767;
        const float* W = (which == 0) ? Wq : (which == 1) ? Wk : Wv;
        v0 = W[2 * jj]; v1 = W[2 * jj + 1]; oh = g_wsh; ol = g_wsl; idx = j;
    }
    uint32_t hp, lp;
    split2(v0, v1, hp, lp);
    oh[idx] = hp;
    ol[idx] = lp;
}

// ============================================================================
// Kernel 1: QKV projection, split-bf16 m16n8k16 (3-MMA), ldmatrix frags.
// 64x64 tile, 256 thr, K=256 in 8 chunks of 32, double-buffered, 1 sync/chunk.
// ============================================================================
#define PJ_STRIDE 20
__global__ __launch_bounds__(256, 2) void proj_kernel(
    const float* __restrict__ Xq, const float* __restrict__ Xk,
    const float* __restrict__ Xv,
    const float* __restrict__ bq, const float* __restrict__ bk,
    const float* __restrict__ bv)
{
    const int which = blockIdx.z;
    const float* X    = (which == 0) ? Xq : (which == 1) ? Xk : Xv;
    const float* bias = (which == 0) ? bq : (which == 1) ? bk : bv;
    uint32_t* outh    = (which == 0) ? g_qh : (which == 1) ? g_kh : g_vh;
    uint32_t* outl    = (which == 0) ? g_ql : (which == 1) ? g_kl : g_vl;
    const uint32_t* wh_base = g_wsh + which * (D_ * D_ / 2);
    const uint32_t* wl_base = g_wsl + which * (D_ * D_ / 2);

    const int r0 = blockIdx.x * 64;
    const int j0 = blockIdx.y * 64;

    __shared__ uint32_t Xh[2][64 * PJ_STRIDE], Xl[2][64 * PJ_STRIDE];
    __shared__ uint32_t Wh[2][64 * PJ_STRIDE], Wl[2][64 * PJ_STRIDE];

    const int tid  = threadIdx.x;
    const int w    = tid >> 5;
    const int lane = tid & 31;
    const int gid  = lane >> 2;
    const int tg   = lane & 3;
    const int wr   = w & 3;
    const int wc   = w >> 2;

    const int srow = tid >> 2;
    const int sc   = tid & 3;

    // ---- ldmatrix lane addresses (byte offsets within one buffer) ----
    const int lr = lane & 7;
    // A frags: tiles (rg0,q0),(rg1,q0),(rg0,q1),(rg1,q1); rg=(lane>>3)&1, q=lane>>4
    const uint32_t offA = (uint32_t)(((wr * 16 + ((lane >> 3) & 1) * 8 + lr) * PJ_STRIDE
                                      + (lane >> 4) * 4) * 4);
    // B frags: tiles (ns0,q0),(ns0,q1),(ns1,q0),(ns1,q1); nsd=lane>>4, q=(lane>>3)&1
    const uint32_t offB = (uint32_t)(((wc * 32 + (lane >> 4) * 8 + lr) * PJ_STRIDE
                                      + ((lane >> 3) & 1) * 4) * 4);
    const uint32_t xh_b = (uint32_t)__cvta_generic_to_shared(Xh);
    const uint32_t xl_b = (uint32_t)__cvta_generic_to_shared(Xl);
    const uint32_t wh_b = (uint32_t)__cvta_generic_to_shared(Wh);
    const uint32_t wl_b = (uint32_t)__cvta_generic_to_shared(Wl);
    const uint32_t BUFB = 64 * PJ_STRIDE * 4;   // bytes per buffer

    float4 xa = *(const float4*)&X[(size_t)(r0 + srow) * D_ + sc * 8];
    float4 xb = *(const float4*)&X[(size_t)(r0 + srow) * D_ + sc * 8 + 4];
    uint4  wh = *(const uint4*)&wh_base[(size_t)(j0 + srow) * (D_ / 2) + sc * 4];
    uint4  wl = *(const uint4*)&wl_base[(size_t)(j0 + srow) * (D_ / 2) + sc * 4];

    float hh[4][4] = {}, hl[4][4] = {}, lh[4][4] = {};

    for (int mc = 0; mc < 8; mc++) {
        const int bsel = mc & 1;
        {
            uint4 xh4, xl4;
            split2(xa.x, xa.y, xh4.x, xl4.x);
            split2(xa.z, xa.w, xh4.y, xl4.y);
            split2(xb.x, xb.y, xh4.z, xl4.z);
            split2(xb.z, xb.w, xh4.w, xl4.w);
            *(uint4*)&Xh[bsel][srow * PJ_STRIDE + sc * 4] = xh4;
            *(uint4*)&Xl[bsel][srow * PJ_STRIDE + sc * 4] = xl4;
            *(uint4*)&Wh[bsel][srow * PJ_STRIDE + sc * 4] = wh;
            *(uint4*)&Wl[bsel][srow * PJ_STRIDE + sc * 4] = wl;
        }
        if (mc < 7) {
            const int kc = (mc + 1) * 32;
            xa = *(const float4*)&X[(size_t)(r0 + srow) * D_ + kc + sc * 8];
            xb = *(const float4*)&X[(size_t)(r0 + srow) * D_ + kc + sc * 8 + 4];
            wh = *(const uint4*)&wh_base[(size_t)(j0 + srow) * (D_ / 2) + kc / 2 + sc * 4];
            wl = *(const uint4*)&wl_base[(size_t)(j0 + srow) * (D_ / 2) + kc / 2 + sc * 4];
        }
        __syncthreads();

        const uint32_t bo = bsel * BUFB;
#pragma unroll
        for (int kb = 0; kb < 2; kb++) {
            uint32_t ah4[4], al4[4];
            ldsm4(ah4, xh_b + bo + offA + kb * 32);
            ldsm4(al4, xl_b + bo + offA + kb * 32);
#pragma unroll
            for (int np = 0; np < 2; np++) {
                uint32_t bh4[4], bl4[4];
                const uint32_t boff = bo + offB + np * (16 * PJ_STRIDE * 4) + kb * 32;
                ldsm4(bh4, wh_b + boff);
                ldsm4(bl4, wl_b + boff);
                mma16(hh[np * 2],     ah4, bh4);
                mma16(hl[np * 2],     ah4, bl4);
                mma16(lh[np * 2],     al4, bh4);
                mma16(hh[np * 2 + 1], ah4, bh4 + 2);
                mma16(hl[np * 2 + 1], ah4, bl4 + 2);
                mma16(lh[np * 2 + 1], al4, bh4 + 2);
            }
        }
        // no trailing sync: double buffers + next barrier protect reuse
    }

#pragma unroll
    for (int ns = 0; ns < 4; ns++) {
        const int col = j0 + wc * 32 + ns * 8 + 2 * tg;
        const float b0 = bias[col], b1 = bias[col + 1];
        const int h = col >> 6, cpair = (col & 63) >> 1;
#pragma unroll
        for (int half = 0; half < 2; half++) {
            const int r = r0 + wr * 16 + gid + half * 8;
            const int bb = r >> 10, l = r & 1023;
            const size_t idx = (((size_t)(bb * H_ + h) * N_) + l) * CP_ + cpair;
            const float v0 = hh[ns][half * 2 + 0] + hl[ns][half * 2 + 0] + lh[ns][half * 2 + 0] + b0;
            const float v1 = hh[ns][half * 2 + 1] + hl[ns][half * 2 + 1] + lh[ns][half * 2 + 1] + b1;
            uint32_t hp, lp;
            split2(v0, v1, hp, lp);
            outh[idx] = hp;
            outl[idx] = lp;
        }
    }
}

// ============================================================================
// Kernel 2: FUSED sp + scores + (gather/factor/mask fused into softmax) + AV.
// (unchanged from R11 — 512 thr, ldmatrix frags, shared K/V staging)
// ============================================================================
__global__ __launch_bounds__(512, 1) void fused_kernel(
    const float* __restrict__ factor, const int* __restrict__ eidx,
    const unsigned char* __restrict__ kmask,
    float* __restrict__ attn, float* __restrict__ hidden)
{
    extern __shared__ float smf[];
    float*    S   = smf;
    uint32_t* Su  = (uint32_t*)smf;
    uint32_t* KH0 = (uint32_t*)(smf + KH0_OFF);
    uint32_t* KL0 = (uint32_t*)(smf + KL0_OFF);
    uint32_t* KH1 = (uint32_t*)(smf + KH1_OFF);
    uint32_t* KL1 = (uint32_t*)(smf + KL1_OFF);
    float*    Sp  = smf + SP_OFF;

    const int tid  = threadIdx.x;
    const int w    = tid >> 5;
    const int lane = tid & 31;
    const int gid  = lane >> 2;
    const int tg   = lane & 3;
    const int wm   = w & 7;
    const int mt   = w >> 3;
    const int bh = blockIdx.y, b = bh >> 2, h = bh & 3;
    const int n0 = blockIdx.x * 32;
    const int r0 = mt * 16 + gid;

    const int kst_r = tid >> 3;
    const int kst_c = (tid & 7) * 4;

    const uint32_t smem_u = (uint32_t)__cvta_generic_to_shared(smf);
    const int lg = lane >> 3, lr = lane & 7;
    const uint32_t offKB = (uint32_t)(((wm * 8 + lr) * KB_STRIDE + lg * 4) * 4);
    const uint32_t offVB = (uint32_t)(((lg * 8 + lr) * KB_STRIDE + wm * 4) * 4);
    const uint32_t offAh = (uint32_t)(((mt * 16 + (lg & 1) * 8 + lr) * S_STRIDE + (lg >> 1) * 4) * 4);
    const uint32_t KH0b = smem_u + KH0_OFF * 4;
    const uint32_t KL0b = smem_u + KL0_OFF * 4;
    const uint32_t KH1b = smem_u + KH1_OFF * 4;
    const uint32_t KL1b = smem_u + KL1_OFF * 4;

    const uint32_t* kh_base = g_kh + (size_t)bh * M_ * CP_;
    const uint32_t* kl_base = g_kl + (size_t)bh * M_ * CP_;
    const uint32_t* vh_base = g_vh + (size_t)bh * M_ * CP_;
    const uint32_t* vl_base = g_vl + (size_t)bh * M_ * CP_;

    // ---------- stage Q (32 rows x 32 pairs) through KH0/KL0 ----------
    {
        const uint32_t* qh = g_qh + ((size_t)bh * N_ + n0) * CP_;
        const uint32_t* ql = g_ql + ((size_t)bh * N_ + n0) * CP_;
        uint2 q2h = ((const uint2*)qh)[tid];
        uint2 q2l = ((const uint2*)ql)[tid];
        const int qr = tid >> 4, qc = (tid & 15) * 2;
        *(uint2*)&KH0[qr * KB_STRIDE + qc] = q2h;
        *(uint2*)&KL0[qr * KB_STRIDE + qc] = q2l;
    }
    uint4 eph, epl;
    eph = *(const uint4*)&g_eh[(size_t)kst_r * (D_ / 2) + h * CP_ + kst_c];
    epl = *(const uint4*)&g_el[(size_t)kst_r * (D_ / 2) + h * CP_ + kst_c];
    __syncthreads();

    // ---------- preload Q hi+lo fragments (4 k16-blocks) ----------
    uint32_t qfh[4][4], qfl[4][4];
#pragma unroll
    for (int kb = 0; kb < 4; kb++) {
        const int c0 = kb * 8 + tg;
        qfh[kb][0] = KH0[r0 * KB_STRIDE + c0];
        qfh[kb][1] = KH0[(r0 + 8) * KB_STRIDE + c0];
        qfh[kb][2] = KH0[r0 * KB_STRIDE + c0 + 4];
        qfh[kb][3] = KH0[(r0 + 8) * KB_STRIDE + c0 + 4];
        qfl[kb][0] = KL0[r0 * KB_STRIDE + c0];
        qfl[kb][1] = KL0[(r0 + 8) * KB_STRIDE + c0];
        qfl[kb][2] = KL0[r0 * KB_STRIDE + c0 + 4];
        qfl[kb][3] = KL0[(r0 + 8) * KB_STRIDE + c0 + 4];
    }
    __syncthreads();

    // ---------- SP: Sp(32x128) = Q · emb_h^T (2 chunks) ----------
#pragma unroll
    for (int pc = 0; pc < 2; pc++) {
        uint32_t* Khb = pc ? KH1 : KH0;
        uint32_t* Klb = pc ? KL1 : KL0;
        const uint32_t Khbb = pc ? KH1b : KH0b;
        const uint32_t Klbb = pc ? KL1b : KL0b;
        *(uint4*)&Khb[kst_r * KB_STRIDE + kst_c] = eph;
        *(uint4*)&Klb[kst_r * KB_STRIDE + kst_c] = epl;
        if (pc == 0) {
            eph = *(const uint4*)&g_eh[(size_t)(64 + kst_r) * (D_ / 2) + h * CP_ + kst_c];
            epl = *(const uint4*)&g_el[(size_t)(64 + kst_r) * (D_ / 2) + h * CP_ + kst_c];
        }
        __syncthreads();

        float hh[4] = {}, hl[4] = {}, lh[4] = {};
#pragma unroll
        for (int kbp = 0; kbp < 2; kbp++) {
            uint32_t bh4[4], bl4[4];
            ldsm4(bh4, Khbb + offKB + kbp * 64);
            ldsm4(bl4, Klbb + offKB + kbp * 64);
            mma16(hh, qfh[2 * kbp], bh4);
            mma16(hl, qfh[2 * kbp], bl4);
            mma16(lh, qfl[2 * kbp], bh4);
            mma16(hh, qfh[2 * kbp + 1], bh4 + 2);
            mma16(hl, qfh[2 * kbp + 1], bl4 + 2);
            mma16(lh, qfl[2 * kbp + 1], bh4 + 2);
        }
        const int col = pc * 64 + wm * 8 + 2 * tg;
        *(float2*)(Sp + r0 * SP_STRIDE + col) =
            make_float2(hh[0] + hl[0] + lh[0], hh[1] + hl[1] + lh[1]);
        *(float2*)(Sp + (r0 + 8) * SP_STRIDE + col) =
            make_float2(hh[2] + hl[2] + lh[2], hh[3] + hl[3] + lh[3]);
    }
    uint4 kph = *(const uint4*)&kh_base[(size_t)tid * 4];
    uint4 kpl = *(const uint4*)&kl_base[(size_t)tid * 4];

    // ---------- GEMM1: S(32x1024) = Q · K^T (16 chunks, 1 sync each) ----------
    for (int mc = 0; mc < 16; mc++) {
        uint32_t* Khb = (mc & 1) ? KH1 : KH0;
        uint32_t* Klb = (mc & 1) ? KL1 : KL0;
        const uint32_t Khbb = (mc & 1) ? KH1b : KH0b;
        const uint32_t Klbb = (mc & 1) ? KL1b : KL0b;
        *(uint4*)&Khb[kst_r * KB_STRIDE + kst_c] = kph;
        *(uint4*)&Klb[kst_r * KB_STRIDE + kst_c] = kpl;
        if (mc < 15) {
            const size_t off = (size_t)(mc + 1) * 2048;
            kph = *(const uint4*)&kh_base[off + (size_t)tid * 4];
            kpl = *(const uint4*)&kl_base[off + (size_t)tid * 4];
        }
        __syncthreads();

        float hh[4] = {}, hl[4] = {}, lh[4] = {};
#pragma unroll
        for (int kbp = 0; kbp < 2; kbp++) {
            uint32_t bh4[4], bl4[4];
            ldsm4(bh4, Khbb + offKB + kbp * 64);
            ldsm4(bl4, Klbb + offKB + kbp * 64);
            mma16(hh, qfh[2 * kbp], bh4);
            mma16(hl, qfh[2 * kbp], bl4);
            mma16(lh, qfl[2 * kbp], bh4);
            mma16(hh, qfh[2 * kbp + 1], bh4 + 2);
            mma16(hl, qfh[2 * kbp + 1], bl4 + 2);
            mma16(lh, qfl[2 * kbp + 1], bh4 + 2);
        }
        const int col = mc * 64 + wm * 8 + 2 * tg;
        *(float2*)(S + r0 * S_STRIDE + col) =
            make_float2(hh[0] + hl[0] + lh[0], hh[1] + hl[1] + lh[1]);
        *(float2*)(S + (r0 + 8) * S_STRIDE + col) =
            make_float2(hh[2] + hl[2] + lh[2], hh[3] + hl[3] + lh[3]);
    }
    __syncthreads();

    // prefetch V chunk 0 (raw [m][c] copy — same pattern as K)
    uint4 vph = *(const uint4*)&vh_base[(size_t)tid * 4];
    uint4 vpl = *(const uint4*)&vl_base[(size_t)tid * 4];

    // ---------- softmax with FUSED epilogue: warp w owns rows 2w, 2w+1 ----------
#pragma unroll
    for (int rr = 0; rr < 2; rr++) {
        const int row = w * 2 + rr;
        const size_t gb = ((size_t)(b * N_ + n0 + row)) * M_;
        const float* sprow = Sp + row * SP_STRIDE;
        float vals[32];
        float mx = -INFINITY;
#pragma unroll
        for (int j = 0; j < 8; j++) {
            const int c4 = (j * 32 + lane) * 4;
            float4 sc = *(float4*)(S + row * S_STRIDE + c4);
            int4   id = *(const int4*)(eidx + gb + c4);
            float4 fa = *(const float4*)(factor + gb + c4);
            const uchar4 km = *(const uchar4*)(kmask + b * M_ + c4);
            float e0 = km.x ? -INFINITY : fa.x * (sc.x + sprow[id.x]) * 0.125f;
            float e1 = km.y ? -INFINITY : fa.y * (sc.y + sprow[id.y]) * 0.125f;
            float e2 = km.z ? -INFINITY : fa.z * (sc.z + sprow[id.z]) * 0.125f;
            float e3 = km.w ? -INFINITY : fa.w * (sc.w + sprow[id.w]) * 0.125f;
            vals[j * 4 + 0] = e0; vals[j * 4 + 1] = e1;
            vals[j * 4 + 2] = e2; vals[j * 4 + 3] = e3;
            mx = fmaxf(mx, fmaxf(fmaxf(e0, e1), fmaxf(e2, e3)));
        }
#pragma unroll
        for (int off = 16; off > 0; off >>= 1)
            mx = fmaxf(mx, __shfl_xor_sync(0xffffffffu, mx, off));
        float sum = 0.f;
#pragma unroll
        for (int i = 0; i < 32; i++) { vals[i] = __expf(vals[i] - mx); sum += vals[i]; }
#pragma unroll
        for (int off = 16; off > 0; off >>= 1)
            sum += __shfl_xor_sync(0xffffffffu, sum, off);
        const float inv = 1.0f / sum;
        const size_t abase = ((size_t)(bh * N_ + n0 + row)) * M_;
#pragma unroll
        for (int j = 0; j < 8; j++) {
            const int c4 = (j * 32 + lane) * 4;
            const float p0 = vals[j * 4 + 0] * inv, p1 = vals[j * 4 + 1] * inv;
            const float p2 = vals[j * 4 + 2] * inv, p3 = vals[j * 4 + 3] * inv;
            *(float4*)(attn + abase + c4) = make_float4(p0, p1, p2, p3);
            uint32_t hp0, lp0, hp1, lp1;
            split2(p0, p1, hp0, lp0);
            split2(p2, p3, hp1, lp1);
            const int c2 = c4 >> 1;
            *(uint2*)(Su + row * S_STRIDE + c2)          = make_uint2(hp0, hp1);
            *(uint2*)(Su + row * S_STRIDE + LO_OFF + c2) = make_uint2(lp0, lp1);
        }
    }

    // ---------- AV: hidden(32x64) = P · V (16 chunks; V raw + ldsm.trans) ----------
    float avhh[4] = {}, avhl[4] = {}, avlh[4] = {};
    for (int kc = 0; kc < 16; kc++) {
        uint32_t* Vhb = (kc & 1) ? KH1 : KH0;
        uint32_t* Vlb = (kc & 1) ? KL1 : KL0;
        const uint32_t Vhbb = (kc & 1) ? KH1b : KH0b;
        const uint32_t Vlbb = (kc & 1) ? KL1b : KL0b;
        *(uint4*)&Vhb[kst_r * KB_STRIDE + kst_c] = vph;
        *(uint4*)&Vlb[kst_r * KB_STRIDE + kst_c] = vpl;
        if (kc < 15) {
            const size_t off = (size_t)(kc + 1) * 2048;
            vph = *(const uint4*)&vh_base[off + (size_t)tid * 4];
            vpl = *(const uint4*)&vl_base[off + (size_t)tid * 4];
        }
        __syncthreads();

#pragma unroll
        for (int kbp = 0; kbp < 2; kbp++) {
            uint32_t bh4[4], bl4[4];
            ldsm4t(bh4, Vhbb + offVB + kbp * (32 * KB_STRIDE * 4));
            ldsm4t(bl4, Vlbb + offVB + kbp * (32 * KB_STRIDE * 4));
#pragma unroll
            for (int kk = 0; kk < 2; kk++) {
                const int kb = 2 * kbp + kk;
                const uint32_t cboff = (uint32_t)((kc * 32 + kb * 8) * 4);
                uint32_t ah4[4], al4[4];
                ldsm4(ah4, smem_u + offAh + cboff);
                ldsm4(al4, smem_u + offAh + LO_OFF * 4 + cboff);
                mma16(avhh, ah4, bh4 + 2 * kk);
                mma16(avhl, ah4, bl4 + 2 * kk);
                mma16(avlh, al4, bh4 + 2 * kk);
            }
        }
    }

    // store hidden
    {
        const int row = n0 + r0;
        const int col = h * 64 + wm * 8 + 2 * tg;
        *(float2*)(hidden + ((size_t)b * N_ + row) * D_ + col) =
            make_float2(avhh[0] + avhl[0] + avlh[0], avhh[1] + avhl[1] + avlh[1]);
        *(float2*)(hidden + ((size_t)b * N_ + row + 8) * D_ + col) =
            make_float2(avhh[2] + avhl[2] + avlh[2], avhh[3] + avhl[3] + avlh[3]);
    }
}

// ============================================================================
// Launch
// ============================================================================
extern "C" void kernel_launch(void* const* d_in, const int* in_sizes, int n_in,
                              void* d_out, int out_size)
{
    const float* input_q = (const float*)d_in[0];
    const float* input_k = (const float*)d_in[1];
    const float* input_v = (const float*)d_in[2];
    const float* Wq = (const float*)d_in[3];
    const float* bq = (const float*)d_in[4];
    const float* Wk = (const float*)d_in[5];
    const float* bk = (const float*)d_in[6];
    const float* Wv = (const float*)d_in[7];
    const float* bv = (const float*)d_in[8];
    const float* emb_table = (const float*)d_in[9];
    const float* factor = (const float*)d_in[10];
    const int* eidx = (const int*)d_in[11];
    const unsigned char* kmask = (const unsigned char*)d_in[12];

    float* hidden = (float*)d_out;                          // (B,N,D)
    float* attn   = (float*)d_out + (size_t)B_ * N_ * D_;   // (B,H,N,M)

    static int smem_set = 0;
    if (!smem_set) {
        cudaFuncSetAttribute(fused_kernel,
                             cudaFuncAttributeMaxDynamicSharedMemorySize, SMEM_BYTES);
        smem_set = 1;
    }

    split_kernel<<<(P_ * D_ / 2 + 3 * D_ * D_ / 2) / 256, 256>>>(emb_table, Wq, Wk, Wv);

    proj_kernel<<<dim3((B_ * N_) / 64, D_ / 64, 3), 256>>>(
        input_q, input_k, input_v, bq, bk, bv);

    fused_kernel<<<dim3(N_ / 32, B_ * H_), 512, SMEM_BYTES>>>(
        factor, eidx, kmask, attn, hidden);
}

// round 13
// speedup vs baseline: 1.2237x; 1.0097x over previous
#include <cuda_runtime.h>
#include <cuda_bf16.h>
#include <math.h>
#include <stdint.h>

#define B_ 8
#define N_ 1024
#define M_ 1024
#define D_ 256
#define H_ 4
#define P_ 128
#define C_ 64
#define CP_ 32   // C/2 pairs

// -------- device scratch: bf16x2-packed hi/lo operands (pairs along K dim) --------
__device__ uint32_t g_qh[B_ * H_ * N_ * CP_];
__device__ uint32_t g_ql[B_ * H_ * N_ * CP_];
__device__ uint32_t g_kh[B_ * H_ * M_ * CP_];
__device__ uint32_t g_kl[B_ * H_ * M_ * CP_];
__device__ uint32_t g_vh[B_ * H_ * M_ * CP_];
__device__ uint32_t g_vl[B_ * H_ * M_ * CP_];
__device__ uint32_t g_eh[P_ * D_ / 2];
__device__ uint32_t g_el[P_ * D_ / 2];
__device__ uint32_t g_wsh[3 * D_ * D_ / 2];
__device__ uint32_t g_wsl[3 * D_ * D_ / 2];

// ---------------- helpers ----------------
__device__ __forceinline__ void split2(float v0, float v1, uint32_t& hp, uint32_t& lp) {
    __nv_bfloat16 h0 = __float2bfloat16_rn(v0);
    __nv_bfloat16 h1 = __float2bfloat16_rn(v1);
    __nv_bfloat16 l0 = __float2bfloat16_rn(v0 - __bfloat162float(h0));
    __nv_bfloat16 l1 = __float2bfloat16_rn(v1 - __bfloat162float(h1));
    hp = (uint32_t)__bfloat16_as_ushort(h0) | ((uint32_t)__bfloat16_as_ushort(h1) << 16);
    lp = (uint32_t)__bfloat16_as_ushort(l0) | ((uint32_t)__bfloat16_as_ushort(l1) << 16);
}

__device__ __forceinline__ void mma16(float d[4], const uint32_t a[4], const uint32_t b[2]) {
    asm volatile(
        "mma.sync.aligned.m16n8k16.row.col.f32.bf16.bf16.f32 "
        "{%0,%1,%2,%3}, {%4,%5,%6,%7}, {%8,%9}, {%0,%1,%2,%3};"
        : "+f"(d[0]), "+f"(d[1]), "+f"(d[2]), "+f"(d[3])
        : "r"(a[0]), "r"(a[1]), "r"(a[2]), "r"(a[3]), "r"(b[0]), "r"(b[1]));
}

__device__ __forceinline__ void ldsm4(uint32_t r[4], uint32_t a) {
    asm volatile("ldmatrix.sync.aligned.m8n8.x4.shared.b16 {%0,%1,%2,%3}, [%4];"
        : "=r"(r[0]), "=r"(r[1]), "=r"(r[2]), "=r"(r[3]) : "r"(a));
}
__device__ __forceinline__ void ldsm4t(uint32_t r[4], uint32_t a) {
    asm volatile("ldmatrix.sync.aligned.m8n8.x4.trans.shared.b16 {%0,%1,%2,%3}, [%4];"
        : "=r"(r[0]), "=r"(r[1]), "=r"(r[2]), "=r"(r[3]) : "r"(a));
}
__device__ __forceinline__ void cpa16(uint32_t dst, const void* src) {
    asm volatile("cp.async.cg.shared.global [%0], [%1], 16;" :: "r"(dst), "l"(src) : "memory");
}
__device__ __forceinline__ void cp_commit() {
    asm volatile("cp.async.commit_group;" ::: "memory");
}
template <int N> __device__ __forceinline__ void cp_wait() {
    asm volatile("cp.async.wait_group %0;" :: "n"(N) : "memory");
}

// ---------------- fused smem layout (32-bit words) ----------------
#define S_STRIDE  1036   // fp32 logits; packed probs: hi [0,512), lo [520,1032)
#define LO_OFF    520
#define KB_STRIDE 36     // staging: 64 rows x 32 words (+4 pad); 4 buffer pairs
#define KH0_OFF   33152
#define KL0_OFF   35456
#define KH1_OFF   37760
#define KL1_OFF   40064
#define KH2_OFF   42368
#define KL2_OFF   44672
#define KH3_OFF   46976
#define KL3_OFF   49280
#define SP_STRIDE 132
#define SP_OFF    51584
#define SMEM_WORDS 55808
#define SMEM_BYTES (SMEM_WORDS * 4)   // 223232 B

// ============================================================================
// Kernel 0: split W/emb into packed bf16x2 hi/lo pairs (along d).
// ============================================================================
__global__ __launch_bounds__(256) void split_kernel(
    const float* __restrict__ emb, const float* __restrict__ Wq,
    const float* __restrict__ Wk, const float* __restrict__ Wv)
{
    const int i = blockIdx.x * 256 + threadIdx.x;
    float v0, v1;
    uint32_t *oh, *ol;
    int idx;
    if (i < P_ * D_ / 2) {
        v0 = emb[2 * i]; v1 = emb[2 * i + 1]; oh = g_eh; ol = g_el; idx = i;
    } else {
        const int j = i - P_ * D_ / 2;
        const int which = j >> 15;
        const int jj = j & 32767;
        const float* W = (which == 0) ? Wq : (which == 1) ? Wk : Wv;
        v0 = W[2 * jj]; v1 = W[2 * jj + 1]; oh = g_wsh; ol = g_wsl; idx = j;
    }
    uint32_t hp, lp;
    split2(v0, v1, hp, lp);
    oh[idx] = hp;
    ol[idx] = lp;
}

// ============================================================================
// Kernel 1: QKV projection, split-bf16 m16n8k16 (3-MMA), ldmatrix frags.
// (unchanged from R12)
// ============================================================================
#define PJ_STRIDE 20
__global__ __launch_bounds__(256, 2) void proj_kernel(
    const float* __restrict__ Xq, const float* __restrict__ Xk,
    const float* __restrict__ Xv,
    const float* __restrict__ bq, const float* __restrict__ bk,
    const float* __restrict__ bv)
{
    const int which = blockIdx.z;
    const float* X    = (which == 0) ? Xq : (which == 1) ? Xk : Xv;
    const float* bias = (which == 0) ? bq : (which == 1) ? bk : bv;
    uint32_t* outh    = (which == 0) ? g_qh : (which == 1) ? g_kh : g_vh;
    uint32_t* outl    = (which == 0) ? g_ql : (which == 1) ? g_kl : g_vl;
    const uint32_t* wh_base = g_wsh + which * (D_ * D_ / 2);
    const uint32_t* wl_base = g_wsl + which * (D_ * D_ / 2);

    const int r0 = blockIdx.x * 64;
    const int j0 = blockIdx.y * 64;

    __shared__ uint32_t Xh[2][64 * PJ_STRIDE], Xl[2][64 * PJ_STRIDE];
    __shared__ uint32_t Wh[2][64 * PJ_STRIDE], Wl[2][64 * PJ_STRIDE];

    const int tid  = threadIdx.x;
    const int w    = tid >> 5;
    const int lane = tid & 31;
    const int gid  = lane >> 2;
    const int tg   = lane & 3;
    const int wr   = w & 3;
    const int wc   = w >> 2;

    const int srow = tid >> 2;
    const int sc   = tid & 3;

    const int lr = lane & 7;
    const uint32_t offA = (uint32_t)(((wr * 16 + ((lane >> 3) & 1) * 8 + lr) * PJ_STRIDE
                                      + (lane >> 4) * 4) * 4);
    const uint32_t offB = (uint32_t)(((wc * 32 + (lane >> 4) * 8 + lr) * PJ_STRIDE
                                      + ((lane >> 3) & 1) * 4) * 4);
    const uint32_t xh_b = (uint32_t)__cvta_generic_to_shared(Xh);
    const uint32_t xl_b = (uint32_t)__cvta_generic_to_shared(Xl);
    const uint32_t wh_b = (uint32_t)__cvta_generic_to_shared(Wh);
    const uint32_t wl_b = (uint32_t)__cvta_generic_to_shared(Wl);
    const uint32_t BUFB = 64 * PJ_STRIDE * 4;

    float4 xa = *(const float4*)&X[(size_t)(r0 + srow) * D_ + sc * 8];
    float4 xb = *(const float4*)&X[(size_t)(r0 + srow) * D_ + sc * 8 + 4];
    uint4  wh = *(const uint4*)&wh_base[(size_t)(j0 + srow) * (D_ / 2) + sc * 4];
    uint4  wl = *(const uint4*)&wl_base[(size_t)(j0 + srow) * (D_ / 2) + sc * 4];

    float hh[4][4] = {}, hl[4][4] = {}, lh[4][4] = {};

    for (int mc = 0; mc < 8; mc++) {
        const int bsel = mc & 1;
        {
            uint4 xh4, xl4;
            split2(xa.x, xa.y, xh4.x, xl4.x);
            split2(xa.z, xa.w, xh4.y, xl4.y);
            split2(xb.x, xb.y, xh4.z, xl4.z);
            split2(xb.z, xb.w, xh4.w, xl4.w);
            *(uint4*)&Xh[bsel][srow * PJ_STRIDE + sc * 4] = xh4;
            *(uint4*)&Xl[bsel][srow * PJ_STRIDE + sc * 4] = xl4;
            *(uint4*)&Wh[bsel][srow * PJ_STRIDE + sc * 4] = wh;
            *(uint4*)&Wl[bsel][srow * PJ_STRIDE + sc * 4] = wl;
        }
        if (mc < 7) {
            const int kc = (mc + 1) * 32;
            xa = *(const float4*)&X[(size_t)(r0 + srow) * D_ + kc + sc * 8];
            xb = *(const float4*)&X[(size_t)(r0 + srow) * D_ + kc + sc * 8 + 4];
            wh = *(const uint4*)&wh_base[(size_t)(j0 + srow) * (D_ / 2) + kc / 2 + sc * 4];
            wl = *(const uint4*)&wl_base[(size_t)(j0 + srow) * (D_ / 2) + kc / 2 + sc * 4];
        }
        __syncthreads();

        const uint32_t bo = bsel * BUFB;
#pragma unroll
        for (int kb = 0; kb < 2; kb++) {
            uint32_t ah4[4], al4[4];
            ldsm4(ah4, xh_b + bo + offA + kb * 32);
            ldsm4(al4, xl_b + bo + offA + kb * 32);
#pragma unroll
            for (int np = 0; np < 2; np++) {
                uint32_t bh4[4], bl4[4];
                const uint32_t boff = bo + offB + np * (16 * PJ_STRIDE * 4) + kb * 32;
                ldsm4(bh4, wh_b + boff);
                ldsm4(bl4, wl_b + boff);
                mma16(hh[np * 2],     ah4, bh4);
                mma16(hl[np * 2],     ah4, bl4);
                mma16(lh[np * 2],     al4, bh4);
                mma16(hh[np * 2 + 1], ah4, bh4 + 2);
                mma16(hl[np * 2 + 1], ah4, bl4 + 2);
                mma16(lh[np * 2 + 1], al4, bh4 + 2);
            }
        }
    }

#pragma unroll
    for (int ns = 0; ns < 4; ns++) {
        const int col = j0 + wc * 32 + ns * 8 + 2 * tg;
        const float b0 = bias[col], b1 = bias[col + 1];
        const int h = col >> 6, cpair = (col & 63) >> 1;
#pragma unroll
        for (int half = 0; half < 2; half++) {
            const int r = r0 + wr * 16 + gid + half * 8;
            const int bb = r >> 10, l = r & 1023;
            const size_t idx = (((size_t)(bb * H_ + h) * N_) + l) * CP_ + cpair;
            const float v0 = hh[ns][half * 2 + 0] + hl[ns][half * 2 + 0] + lh[ns][half * 2 + 0] + b0;
            const float v1 = hh[ns][half * 2 + 1] + hl[ns][half * 2 + 1] + lh[ns][half * 2 + 1] + b1;
            uint32_t hp, lp;
            split2(v0, v1, hp, lp);
            outh[idx] = hp;
            outl[idx] = lp;
        }
    }
}

// ============================================================================
// Kernel 2: FUSED sp + scores + softmax(+epilogue) + AV.
// 512 threads; cp.async 4-buffer staging ring for K and V; ldmatrix frags.
// ============================================================================
__global__ __launch_bounds__(512, 1) void fused_kernel(
    const float* __restrict__ factor, const int* __restrict__ eidx,
    const unsigned char* __restrict__ kmask,
    float* __restrict__ attn, float* __restrict__ hidden)
{
    extern __shared__ float smf[];
    float*    S   = smf;
    uint32_t* Su  = (uint32_t*)smf;
    uint32_t* KH0 = (uint32_t*)(smf + KH0_OFF);
    uint32_t* KL0 = (uint32_t*)(smf + KL0_OFF);
    uint32_t* KH1 = (uint32_t*)(smf + KH1_OFF);
    uint32_t* KL1 = (uint32_t*)(smf + KL1_OFF);
    float*    Sp  = smf + SP_OFF;

    const int tid  = threadIdx.x;
    const int w    = tid >> 5;
    const int lane = tid & 31;
    const int gid  = lane >> 2;
    const int tg   = lane & 3;
    const int wm   = w & 7;
    const int mt   = w >> 3;
    const int bh = blockIdx.y, b = bh >> 2, h = bh & 3;
    const int n0 = blockIdx.x * 32;
    const int r0 = mt * 16 + gid;

    const int kst_r = tid >> 3;
    const int kst_c = (tid & 7) * 4;
    const uint32_t st_off = (uint32_t)((kst_r * KB_STRIDE + kst_c) * 4);  // bytes

    const uint32_t smem_u = (uint32_t)__cvta_generic_to_shared(smf);
    const int lg = lane >> 3, lr = lane & 7;
    const uint32_t offKB = (uint32_t)(((wm * 8 + lr) * KB_STRIDE + lg * 4) * 4);
    const uint32_t offVB = (uint32_t)(((lg * 8 + lr) * KB_STRIDE + wm * 4) * 4);
    const uint32_t offAh = (uint32_t)(((mt * 16 + (lg & 1) * 8 + lr) * S_STRIDE + (lg >> 1) * 4) * 4);
    // 4 staging buffer base byte-addresses (hi and lo)
    const uint32_t KHb[4] = {smem_u + KH0_OFF * 4, smem_u + KH1_OFF * 4,
                             smem_u + KH2_OFF * 4, smem_u + KH3_OFF * 4};
    const uint32_t KLb[4] = {smem_u + KL0_OFF * 4, smem_u + KL1_OFF * 4,
                             smem_u + KL2_OFF * 4, smem_u + KL3_OFF * 4};

    const uint32_t* kh_base = g_kh + (size_t)bh * M_ * CP_;
    const uint32_t* kl_base = g_kl + (size_t)bh * M_ * CP_;
    const uint32_t* vh_base = g_vh + (size_t)bh * M_ * CP_;
    const uint32_t* vl_base = g_vl + (size_t)bh * M_ * CP_;

    // ---------- stage Q (32 rows x 32 pairs) through buffer 0 ----------
    {
        const uint32_t* qh = g_qh + ((size_t)bh * N_ + n0) * CP_;
        const uint32_t* ql = g_ql + ((size_t)bh * N_ + n0) * CP_;
        uint2 q2h = ((const uint2*)qh)[tid];
        uint2 q2l = ((const uint2*)ql)[tid];
        const int qr = tid >> 4, qc = (tid & 15) * 2;
        *(uint2*)&KH0[qr * KB_STRIDE + qc] = q2h;
        *(uint2*)&KL0[qr * KB_STRIDE + qc] = q2l;
    }
    uint4 eph, epl;
    eph = *(const uint4*)&g_eh[(size_t)kst_r * (D_ / 2) + h * CP_ + kst_c];
    epl = *(const uint4*)&g_el[(size_t)kst_r * (D_ / 2) + h * CP_ + kst_c];
    __syncthreads();

    // ---------- preload Q hi+lo fragments (4 k16-blocks) ----------
    uint32_t qfh[4][4], qfl[4][4];
#pragma unroll
    for (int kb = 0; kb < 4; kb++) {
        const int c0 = kb * 8 + tg;
        qfh[kb][0] = KH0[r0 * KB_STRIDE + c0];
        qfh[kb][1] = KH0[(r0 + 8) * KB_STRIDE + c0];
        qfh[kb][2] = KH0[r0 * KB_STRIDE + c0 + 4];
        qfh[kb][3] = KH0[(r0 + 8) * KB_STRIDE + c0 + 4];
        qfl[kb][0] = KL0[r0 * KB_STRIDE + c0];
        qfl[kb][1] = KL0[(r0 + 8) * KB_STRIDE + c0];
        qfl[kb][2] = KL0[r0 * KB_STRIDE + c0 + 4];
        qfl[kb][3] = KL0[(r0 + 8) * KB_STRIDE + c0 + 4];
    }
    __syncthreads();

    // ---------- SP: Sp(32x128) = Q · emb_h^T (2 chunks through bufs 0,1) ----------
#pragma unroll
    for (int pc = 0; pc < 2; pc++) {
        uint32_t* Khw = pc ? KH1 : KH0;
        uint32_t* Klw = pc ? KL1 : KL0;
        *(uint4*)((char*)Khw + st_off - 0) = eph;   // st_off relative to buffer base
        *(uint4*)((char*)Klw + st_off - 0) = epl;
        if (pc == 0) {
            eph = *(const uint4*)&g_eh[(size_t)(64 + kst_r) * (D_ / 2) + h * CP_ + kst_c];
            epl = *(const uint4*)&g_el[(size_t)(64 + kst_r) * (D_ / 2) + h * CP_ + kst_c];
        }
        __syncthreads();

        float hh[4] = {}, hl[4] = {}, lh[4] = {};
#pragma unroll
        for (int kbp = 0; kbp < 2; kbp++) {
            uint32_t bh4[4], bl4[4];
            ldsm4(bh4, KHb[pc] + offKB + kbp * 64);
            ldsm4(bl4, KLb[pc] + offKB + kbp * 64);
            mma16(hh, qfh[2 * kbp], bh4);
            mma16(hl, qfh[2 * kbp], bl4);
            mma16(lh, qfl[2 * kbp], bh4);
            mma16(hh, qfh[2 * kbp + 1], bh4 + 2);
            mma16(hl, qfh[2 * kbp + 1], bl4 + 2);
            mma16(lh, qfl[2 * kbp + 1], bh4 + 2);
        }
        const int col = pc * 64 + wm * 8 + 2 * tg;
        *(float2*)(Sp + r0 * SP_STRIDE + col) =
            make_float2(hh[0] + hl[0] + lh[0], hh[1] + hl[1] + lh[1]);
        *(float2*)(Sp + (r0 + 8) * SP_STRIDE + col) =
            make_float2(hh[2] + hl[2] + lh[2], hh[3] + hl[3] + lh[3]);
    }
    __syncthreads();   // all SP reads done before cp.async overwrites bufs 0,1

    // ---------- GEMM1 prologue: issue K chunks 0..2 into bufs 0..2 ----------
#pragma unroll
    for (int p = 0; p < 3; p++) {
        cpa16(KHb[p] + st_off, kh_base + (size_t)p * 2048 + tid * 4);
        cpa16(KLb[p] + st_off, kl_base + (size_t)p * 2048 + tid * 4);
        cp_commit();
    }

    // ---------- GEMM1: S(32x1024) = Q · K^T (16 chunks, 4-buffer ring) ----------
    for (int mc = 0; mc < 16; mc++) {
        cp_wait<2>();
        __syncthreads();
        if (mc + 3 < 16) {
            const int bi = (mc + 3) & 3;
            cpa16(KHb[bi] + st_off, kh_base + (size_t)(mc + 3) * 2048 + tid * 4);
            cpa16(KLb[bi] + st_off, kl_base + (size_t)(mc + 3) * 2048 + tid * 4);
        }
        cp_commit();   // always commit (empty groups keep wait arithmetic uniform)

        const int bi = mc & 3;
        float hh[4] = {}, hl[4] = {}, lh[4] = {};
#pragma unroll
        for (int kbp = 0; kbp < 2; kbp++) {
            uint32_t bh4[4], bl4[4];
            ldsm4(bh4, KHb[bi] + offKB + kbp * 64);
            ldsm4(bl4, KLb[bi] + offKB + kbp * 64);
            mma16(hh, qfh[2 * kbp], bh4);
            mma16(hl, qfh[2 * kbp], bl4);
            mma16(lh, qfl[2 * kbp], bh4);
            mma16(hh, qfh[2 * kbp + 1], bh4 + 2);
            mma16(hl, qfh[2 * kbp + 1], bl4 + 2);
            mma16(lh, qfl[2 * kbp + 1], bh4 + 2);
        }
        const int col = mc * 64 + wm * 8 + 2 * tg;
        *(float2*)(S + r0 * S_STRIDE + col) =
            make_float2(hh[0] + hl[0] + lh[0], hh[1] + hl[1] + lh[1]);
        *(float2*)(S + (r0 + 8) * S_STRIDE + col) =
            make_float2(hh[2] + hl[2] + lh[2], hh[3] + hl[3] + lh[3]);
    }
    __syncthreads();   // all GEMM1 reads/writes done

    // ---------- AV prologue: issue V chunks 0..2 (loads overlap softmax) ----------
#pragma unroll
    for (int p = 0; p < 3; p++) {
        cpa16(KHb[p] + st_off, vh_base + (size_t)p * 2048 + tid * 4);
        cpa16(KLb[p] + st_off, vl_base + (size_t)p * 2048 + tid * 4);
        cp_commit();
    }

    // ---------- softmax with fused epilogue: warp w owns rows 2w, 2w+1 ----------
#pragma unroll
    for (int rr = 0; rr < 2; rr++) {
        const int row = w * 2 + rr;
        const size_t gb = ((size_t)(b * N_ + n0 + row)) * M_;
        const float* sprow = Sp + row * SP_STRIDE;
        float vals[32];
        float mx = -INFINITY;
#pragma unroll
        for (int j = 0; j < 8; j++) {
            const int c4 = (j * 32 + lane) * 4;
            float4 sc = *(float4*)(S + row * S_STRIDE + c4);
            int4   id = *(const int4*)(eidx + gb + c4);
            float4 fa = *(const float4*)(factor + gb + c4);
            const uchar4 km = *(const uchar4*)(kmask + b * M_ + c4);
            float e0 = km.x ? -INFINITY : fa.x * (sc.x + sprow[id.x]) * 0.125f;
            float e1 = km.y ? -INFINITY : fa.y * (sc.y + sprow[id.y]) * 0.125f;
            float e2 = km.z ? -INFINITY : fa.z * (sc.z + sprow[id.z]) * 0.125f;
            float e3 = km.w ? -INFINITY : fa.w * (sc.w + sprow[id.w]) * 0.125f;
            vals[j * 4 + 0] = e0; vals[j * 4 + 1] = e1;
            vals[j * 4 + 2] = e2; vals[j * 4 + 3] = e3;
            mx = fmaxf(mx, fmaxf(fmaxf(e0, e1), fmaxf(e2, e3)));
        }
#pragma unroll
        for (int off = 16; off > 0; off >>= 1)
            mx = fmaxf(mx, __shfl_xor_sync(0xffffffffu, mx, off));
        float sum = 0.f;
#pragma unroll
        for (int i = 0; i < 32; i++) { vals[i] = __expf(vals[i] - mx); sum += vals[i]; }
#pragma unroll
        for (int off = 16; off > 0; off >>= 1)
            sum += __shfl_xor_sync(0xffffffffu, sum, off);
        const float inv = 1.0f / sum;
        const size_t abase = ((size_t)(bh * N_ + n0 + row)) * M_;
#pragma unroll
        for (int j = 0; j < 8; j++) {
            const int c4 = (j * 32 + lane) * 4;
            const float p0 = vals[j * 4 + 0] * inv, p1 = vals[j * 4 + 1] * inv;
            const float p2 = vals[j * 4 + 2] * inv, p3 = vals[j * 4 + 3] * inv;
            *(float4*)(attn + abase + c4) = make_float4(p0, p1, p2, p3);
            uint32_t hp0, lp0, hp1, lp1;
            split2(p0, p1, hp0, lp0);
            split2(p2, p3, hp1, lp1);
            const int c2 = c4 >> 1;
            *(uint2*)(Su + row * S_STRIDE + c2)          = make_uint2(hp0, hp1);
            *(uint2*)(Su + row * S_STRIDE + LO_OFF + c2) = make_uint2(lp0, lp1);
        }
    }

    // ---------- AV: hidden(32x64) = P · V (16 chunks, 4-buffer ring) ----------
    float avhh[4] = {}, avhl[4] = {}, avlh[4] = {};
    for (int kc = 0; kc < 16; kc++) {
        cp_wait<2>();
        __syncthreads();   // also orders softmax Su writes before first AV reads
        if (kc + 3 < 16) {
            const int bi = (kc + 3) & 3;
            cpa16(KHb[bi] + st_off, vh_base + (size_t)(kc + 3) * 2048 + tid * 4);
            cpa16(KLb[bi] + st_off, vl_base + (size_t)(kc + 3) * 2048 + tid * 4);
        }
        cp_commit();

        const int bi = kc & 3;
#pragma unroll
        for (int kbp = 0; kbp < 2; kbp++) {
            uint32_t bh4[4], bl4[4];
            ldsm4t(bh4, KHb[bi] + offVB + kbp * (32 * KB_STRIDE * 4));
            ldsm4t(bl4, KLb[bi] + offVB + kbp * (32 * KB_STRIDE * 4));
#pragma unroll
            for (int kk = 0; kk < 2; kk++) {
                const int kb = 2 * kbp + kk;
                const uint32_t cboff = (uint32_t)((kc * 32 + kb * 8) * 4);
                uint32_t ah4[4], al4[4];
                ldsm4(ah4, smem_u + offAh + cboff);
                ldsm4(al4, smem_u + offAh + LO_OFF * 4 + cboff);
                mma16(avhh, ah4, bh4 + 2 * kk);
                mma16(avhl, ah4, bl4 + 2 * kk);
                mma16(avlh, al4, bh4 + 2 * kk);
            }
        }
    }

    // store hidden
    {
        const int row = n0 + r0;
        const int col = h * 64 + wm * 8 + 2 * tg;
        *(float2*)(hidden + ((size_t)b * N_ + row) * D_ + col) =
            make_float2(avhh[0] + avhl[0] + avlh[0], avhh[1] + avhl[1] + avlh[1]);
        *(float2*)(hidden + ((size_t)b * N_ + row + 8) * D_ + col) =
            make_float2(avhh[2] + avhl[2] + avlh[2], avhh[3] + avhl[3] + avlh[3]);
    }
}

// ============================================================================
// Launch
// ============================================================================
extern "C" void kernel_launch(void* const* d_in, const int* in_sizes, int n_in,
                              void* d_out, int out_size)
{
    const float* input_q = (const float*)d_in[0];
    const float* input_k = (const float*)d_in[1];
    const float* input_v = (const float*)d_in[2];
    const float* Wq = (const float*)d_in[3];
    const float* bq = (const float*)d_in[4];
    const float* Wk = (const float*)d_in[5];
    const float* bk = (const float*)d_in[6];
    const float* Wv = (const float*)d_in[7];
    const float* bv = (const float*)d_in[8];
    const float* emb_table = (const float*)d_in[9];
    const float* factor = (const float*)d_in[10];
    const int* eidx = (const int*)d_in[11];
    const unsigned char* kmask = (const unsigned char*)d_in[12];

    float* hidden = (float*)d_out;                          // (B,N,D)
    float* attn   = (float*)d_out + (size_t)B_ * N_ * D_;   // (B,H,N,M)

    static int smem_set = 0;
    if (!smem_set) {
        cudaFuncSetAttribute(fused_kernel,
                             cudaFuncAttributeMaxDynamicSharedMemorySize, SMEM_BYTES);
        smem_set = 1;
    }

    split_kernel<<<(P_ * D_ / 2 + 3 * D_ * D_ / 2) / 256, 256>>>(emb_table, Wq, Wk, Wv);

    proj_kernel<<<dim3((B_ * N_) / 64, D_ / 64, 3), 256>>>(
        input_q, input_k, input_v, bq, bk, bv);

    fused_kernel<<<dim3(N_ / 32, B_ * H_), 512, SMEM_BYTES>>>(
        factor, eidx, kmask, attn, hidden);
}